// round 5
// baseline (speedup 1.0000x reference)
#include <cuda_runtime.h>
#include <cuda_bf16.h>
#include <math.h>
#include <stdint.h>

#define MROWS 8192           // B*T = 4*2048
#define CDIM  768
#define TSEQ  2048
#define NBATCH 4
#define NHEAD 12
#define HD    64

// ---------------- scratch (no allocations allowed) ----------------
__device__ __nv_bfloat16 g_lnh[(size_t)MROWS * CDIM];
__device__ __nv_bfloat16 g_lnl[(size_t)MROWS * CDIM];
__device__ __nv_bfloat16 g_qkvh[(size_t)MROWS * 3 * CDIM];
__device__ __nv_bfloat16 g_qkvl[(size_t)MROWS * 3 * CDIM];
__device__ __nv_bfloat16 g_atth[(size_t)MROWS * CDIM];
__device__ __nv_bfloat16 g_attl[(size_t)MROWS * CDIM];
__device__ float         g_x1 [(size_t)MROWS * CDIM];
__device__ __nv_bfloat16 g_fch[(size_t)MROWS * 4 * CDIM];
__device__ __nv_bfloat16 g_fcl[(size_t)MROWS * 4 * CDIM];

#define W_QKV_N (768*2304)
#define W_PROJ_N (768*768)
#define W_FC_N (768*3072)
#define W_MP_N (3072*768)
__device__ __nv_bfloat16 g_wh[W_QKV_N + W_PROJ_N + W_FC_N + W_MP_N];
__device__ __nv_bfloat16 g_wl[W_QKV_N + W_PROJ_N + W_FC_N + W_MP_N];

// ---------------- helpers ----------------
__device__ __forceinline__ float warp_sum(float v) {
#pragma unroll
    for (int m = 16; m; m >>= 1) v += __shfl_xor_sync(0xffffffffu, v, m);
    return v;
}

__device__ __forceinline__ float gelu_tanh(float x) {
    const float c = 0.7978845608028654f;  // sqrt(2/pi)
    float x3 = x * x * x;
    return 0.5f * x * (1.0f + tanhf(c * (x + 0.044715f * x3)));
}

__device__ __forceinline__ uint32_t smem_u32(const void* p) {
    return (uint32_t)__cvta_generic_to_shared(p);
}

__device__ __forceinline__ void cp16(uint32_t dst, const void* src) {
    asm volatile("cp.async.cg.shared.global [%0], [%1], 16;\n" :: "r"(dst), "l"(src));
}
__device__ __forceinline__ void cp_commit() { asm volatile("cp.async.commit_group;\n"); }
template<int N> __device__ __forceinline__ void cp_wait() {
    asm volatile("cp.async.wait_group %0;\n" :: "n"(N));
}

__device__ __forceinline__ void ldsm_x4(uint32_t (&r)[4], uint32_t addr) {
    asm volatile("ldmatrix.sync.aligned.m8n8.x4.shared.b16 {%0,%1,%2,%3}, [%4];"
        : "=r"(r[0]), "=r"(r[1]), "=r"(r[2]), "=r"(r[3]) : "r"(addr));
}
__device__ __forceinline__ void ldsm_x4t(uint32_t (&r)[4], uint32_t addr) {
    asm volatile("ldmatrix.sync.aligned.m8n8.x4.trans.shared.b16 {%0,%1,%2,%3}, [%4];"
        : "=r"(r[0]), "=r"(r[1]), "=r"(r[2]), "=r"(r[3]) : "r"(addr));
}
__device__ __forceinline__ void mma16816(float (&d)[4], const uint32_t (&a)[4],
                                         const uint32_t (&b)[2]) {
    asm volatile(
        "mma.sync.aligned.m16n8k16.row.col.f32.bf16.bf16.f32 "
        "{%0,%1,%2,%3},{%4,%5,%6,%7},{%8,%9},{%0,%1,%2,%3};"
        : "+f"(d[0]), "+f"(d[1]), "+f"(d[2]), "+f"(d[3])
        : "r"(a[0]), "r"(a[1]), "r"(a[2]), "r"(a[3]), "r"(b[0]), "r"(b[1]));
}

__device__ __forceinline__ void split_bf16(float v, __nv_bfloat16& h, __nv_bfloat16& l) {
    h = __float2bfloat16(v);
    l = __float2bfloat16(v - __bfloat162float(h));
}

__device__ __forceinline__ void packsplit(float x0, float x1, uint32_t& h, uint32_t& l) {
    __nv_bfloat16 h0, h1, l0, l1;
    split_bf16(x0, h0, l0);
    split_bf16(x1, h1, l1);
    __nv_bfloat162 hv(h0, h1), lv(l0, l1);
    h = *(uint32_t*)&hv;
    l = *(uint32_t*)&lv;
}

// ---------------- weight split: f32 -> bf16 hi/lo --------------------
__global__ __launch_bounds__(256) void split4_kernel(
    const float4* __restrict__ s, __nv_bfloat162* __restrict__ h,
    __nv_bfloat162* __restrict__ l, int n4)
{
    int i = blockIdx.x * 256 + threadIdx.x;
    if (i >= n4) return;
    float4 v = s[i];
    __nv_bfloat16 h0, h1, h2, h3, l0, l1, l2, l3;
    split_bf16(v.x, h0, l0); split_bf16(v.y, h1, l1);
    split_bf16(v.z, h2, l2); split_bf16(v.w, h3, l3);
    h[2 * i]     = __nv_bfloat162(h0, h1);
    h[2 * i + 1] = __nv_bfloat162(h2, h3);
    l[2 * i]     = __nv_bfloat162(l0, l1);
    l[2 * i + 1] = __nv_bfloat162(l2, l3);
}

// ---------------- LayerNorm (row = 768, ddof=1) -> bf16 hi/lo --------
__global__ __launch_bounds__(256) void ln_split_kernel(
    const float* __restrict__ x, const float* __restrict__ w,
    const float* __restrict__ b, __nv_bfloat16* __restrict__ yh,
    __nv_bfloat16* __restrict__ yl)
{
    const int row = blockIdx.x;
    const float* xr = x + (size_t)row * CDIM;
    const int t = threadIdx.x;

    float v0 = xr[t], v1 = xr[t + 256], v2 = xr[t + 512];
    float s  = v0 + v1 + v2;
    float s2 = v0 * v0 + v1 * v1 + v2 * v2;

    __shared__ float sh[2][8];
    s = warp_sum(s); s2 = warp_sum(s2);
    int wid = t >> 5, lane = t & 31;
    if (lane == 0) { sh[0][wid] = s; sh[1][wid] = s2; }
    __syncthreads();
    if (wid == 0) {
        float a = (lane < 8) ? sh[0][lane] : 0.0f;
        float c = (lane < 8) ? sh[1][lane] : 0.0f;
        a = warp_sum(a); c = warp_sum(c);
        if (lane == 0) { sh[0][0] = a; sh[1][0] = c; }
    }
    __syncthreads();
    s = sh[0][0]; s2 = sh[1][0];

    float mean = s * (1.0f / (float)CDIM);
    float var  = (s2 - (float)CDIM * mean * mean) * (1.0f / (float)(CDIM - 1));
    float rstd = rsqrtf(var + 1e-5f);

    size_t base = (size_t)row * CDIM;
#pragma unroll
    for (int j = 0; j < 3; j++) {
        int c = t + j * 256;
        float v = (j == 0 ? v0 : (j == 1 ? v1 : v2));
        float y = (v - mean) * rstd * w[c] + b[c];
        __nv_bfloat16 hh, ll;
        split_bf16(y, hh, ll);
        yh[base + c] = hh;
        yl[base + c] = ll;
    }
}

// ---------------- bf16x3 tensor-core GEMM v2 -------------------------
// CTA tile 256x128x32, warp tile 64x64, 3-stage cp.async, 1 sync/iter.
#define APITCH 40
#define BPITCH 136
#define A_STAGE (256 * APITCH)
#define B_STAGE (32 * BPITCH)
#define GEMM_SMEM_BYTES ((2 * 3 * A_STAGE + 2 * 3 * B_STAGE) * 2)

template<int EPI, bool STOREF, bool SPLIT>
__global__ __launch_bounds__(256, 1) void hgemm(
    int M, int N, int K,
    const __nv_bfloat16* __restrict__ Ah, const __nv_bfloat16* __restrict__ Al,
    const __nv_bfloat16* __restrict__ Bh, const __nv_bfloat16* __restrict__ Bl,
    const float* __restrict__ bias, const float* __restrict__ Res,
    float* __restrict__ C, __nv_bfloat16* __restrict__ Ch,
    __nv_bfloat16* __restrict__ Cl)
{
    extern __shared__ __nv_bfloat16 sm[];
    __nv_bfloat16* sAh = sm;                       // [3][256][40]
    __nv_bfloat16* sAl = sAh + 3 * A_STAGE;
    __nv_bfloat16* sBh = sAl + 3 * A_STAGE;        // [3][32][136]
    __nv_bfloat16* sBl = sBh + 3 * B_STAGE;
    const uint32_t uAh = smem_u32(sAh), uAl = smem_u32(sAl);
    const uint32_t uBh = smem_u32(sBh), uBl = smem_u32(sBl);

    const int tid  = threadIdx.x;
    const int warp = tid >> 5, lane = tid & 31;
    const int wr = warp & 3, wc = warp >> 2;       // 4 x 2 warp grid
    const int bm = blockIdx.y * 256, bn = blockIdx.x * 128;

    float acc[4][8][4];
#pragma unroll
    for (int i = 0; i < 4; i++)
#pragma unroll
        for (int j = 0; j < 8; j++)
#pragma unroll
            for (int k = 0; k < 4; k++) acc[i][j][k] = 0.0f;

    auto load_tile = [&](int kt, int stg) {
#pragma unroll
        for (int i = 0; i < 4; i++) {
            int id = tid + i * 256;
            int r = id >> 2, c = (id & 3) * 8;
            uint32_t off = (uint32_t)(stg * A_STAGE + r * APITCH + c) * 2;
            size_t g = (size_t)(bm + r) * K + kt * 32 + c;
            cp16(uAh + off, Ah + g);
            cp16(uAl + off, Al + g);
        }
#pragma unroll
        for (int i = 0; i < 2; i++) {
            int id = tid + i * 256;
            int r = id >> 4, c = (id & 15) * 8;
            uint32_t off = (uint32_t)(stg * B_STAGE + r * BPITCH + c) * 2;
            size_t g = (size_t)(kt * 32 + r) * N + bn + c;
            cp16(uBh + off, Bh + g);
            cp16(uBl + off, Bl + g);
        }
    };

    const int KT = K >> 5;
    load_tile(0, 0);
    cp_commit();
    load_tile(1, 1);
    cp_commit();

    for (int kt = 0; kt < KT; ++kt) {
        const int stg = kt % 3;
        if (kt + 1 < KT) cp_wait<1>(); else cp_wait<0>();
        __syncthreads();
        if (kt + 2 < KT) {
            load_tile(kt + 2, (kt + 2) % 3);
            cp_commit();
        }

#pragma unroll
        for (int ks = 0; ks < 2; ++ks) {
            uint32_t ah[4][4], al[4][4];
#pragma unroll
            for (int ti = 0; ti < 4; ++ti) {
                int r = wr * 64 + ti * 16 + (lane & 15);
                int col = ks * 16 + (lane >> 4) * 8;
                uint32_t off = (uint32_t)(stg * A_STAGE + r * APITCH + col) * 2;
                ldsm_x4(ah[ti], uAh + off);
                ldsm_x4(al[ti], uAl + off);
            }
#pragma unroll
            for (int p = 0; p < 4; ++p) {
                int kr = ks * 16 + (lane & 15);
                int col = wc * 64 + p * 16 + (lane >> 4) * 8;
                uint32_t off = (uint32_t)(stg * B_STAGE + kr * BPITCH + col) * 2;
                uint32_t bh4[4], bl4[4];
                ldsm_x4t(bh4, uBh + off);
                ldsm_x4t(bl4, uBl + off);
                uint32_t b0h[2] = {bh4[0], bh4[1]}, b1h[2] = {bh4[2], bh4[3]};
                uint32_t b0l[2] = {bl4[0], bl4[1]}, b1l[2] = {bl4[2], bl4[3]};
#pragma unroll
                for (int ti = 0; ti < 4; ++ti) {
                    mma16816(acc[ti][2 * p],     ah[ti], b0h);
                    mma16816(acc[ti][2 * p],     ah[ti], b0l);
                    mma16816(acc[ti][2 * p],     al[ti], b0h);
                    mma16816(acc[ti][2 * p + 1], ah[ti], b1h);
                    mma16816(acc[ti][2 * p + 1], ah[ti], b1l);
                    mma16816(acc[ti][2 * p + 1], al[ti], b1h);
                }
            }
        }
    }
    __syncthreads();

    const int row_base = bm + wr * 64;
    const int col_base = bn + wc * 64;
#pragma unroll
    for (int ti = 0; ti < 4; ++ti) {
        int r0 = row_base + ti * 16 + (lane >> 2);
#pragma unroll
        for (int nj = 0; nj < 8; ++nj) {
            int col = col_base + nj * 8 + (lane & 3) * 2;
            float b0 = bias[col], b1 = bias[col + 1];
            float v00 = acc[ti][nj][0] + b0, v01 = acc[ti][nj][1] + b1;
            float v10 = acc[ti][nj][2] + b0, v11 = acc[ti][nj][3] + b1;
            if (EPI == 1) {
                v00 = gelu_tanh(v00); v01 = gelu_tanh(v01);
                v10 = gelu_tanh(v10); v11 = gelu_tanh(v11);
            }
            size_t o0 = (size_t)r0 * N + col;
            size_t o1 = (size_t)(r0 + 8) * N + col;
            if (EPI == 2) {
                v00 += Res[o0]; v01 += Res[o0 + 1];
                v10 += Res[o1]; v11 += Res[o1 + 1];
            }
            if (STOREF) {
                float2 f0; f0.x = v00; f0.y = v01;
                float2 f1; f1.x = v10; f1.y = v11;
                *(float2*)(C + o0) = f0;
                *(float2*)(C + o1) = f1;
            }
            if (SPLIT) {
                uint32_t h0, l0, h1, l1;
                packsplit(v00, v01, h0, l0);
                packsplit(v10, v11, h1, l1);
                *(uint32_t*)(Ch + o0) = h0;
                *(uint32_t*)(Ch + o1) = h1;
                *(uint32_t*)(Cl + o0) = l0;
                *(uint32_t*)(Cl + o1) = l1;
            }
        }
    }
}

// ---------------- Flash attention, bf16x3 tensor cores ----------------
// Br=128 (8 warps), Bc=64. qkv split hi/lo, [row][3C] layout.
#define FAP 72
#define FA_Q_ELEMS (128 * FAP)
#define FA_KV_ELEMS (64 * FAP)
#define FA2_SMEM ((2 * FA_Q_ELEMS + 8 * FA_KV_ELEMS) * 2)

__global__ __launch_bounds__(256) void flash_attn_tc(
    const __nv_bfloat16* __restrict__ qh_g, const __nv_bfloat16* __restrict__ ql_g,
    __nv_bfloat16* __restrict__ outh, __nv_bfloat16* __restrict__ outl)
{
    extern __shared__ __nv_bfloat16 sb[];
    __nv_bfloat16* sQh = sb;                      // [128][72]
    __nv_bfloat16* sQl = sQh + FA_Q_ELEMS;
    __nv_bfloat16* sKV = sQl + FA_Q_ELEMS;        // [2][Kh,Kl,Vh,Vl][64][72]

    const int tid = threadIdx.x, lane = tid & 31, w = tid >> 5;
    const int b = blockIdx.z, h = blockIdx.y, qtb = blockIdx.x;
    const int q0 = qtb * 128;
    const size_t rs = 3 * CDIM;
    const __nv_bfloat16* baseh = qh_g + (size_t)b * TSEQ * rs + h * HD;
    const __nv_bfloat16* basel = ql_g + (size_t)b * TSEQ * rs + h * HD;

    // load Q tile (128 rows x 64 dims, hi+lo)
#pragma unroll
    for (int i = 0; i < 4; i++) {
        int id = tid + i * 256;
        int r = id >> 3, c8 = id & 7;
        size_t g = (size_t)(q0 + r) * rs + c8 * 8;
        cp16(smem_u32(sQh + r * FAP + c8 * 8), baseh + g);
        cp16(smem_u32(sQl + r * FAP + c8 * 8), basel + g);
    }

    auto loadKV = [&](int kt, int buf) {
        const int k0 = kt * 64;
        __nv_bfloat16* d = sKV + buf * 4 * FA_KV_ELEMS;
        const __nv_bfloat16* srcs[4] = { baseh + CDIM, basel + CDIM,
                                         baseh + 2 * CDIM, basel + 2 * CDIM };
#pragma unroll
        for (int a = 0; a < 4; a++) {
#pragma unroll
            for (int i = 0; i < 2; i++) {
                int id = tid + i * 256;
                int r = id >> 3, c8 = id & 7;
                cp16(smem_u32(d + a * FA_KV_ELEMS + r * FAP + c8 * 8),
                     srcs[a] + (size_t)(k0 + r) * rs + c8 * 8);
            }
        }
    };

    loadKV(0, 0);
    cp_commit();

    float o[8][4];
#pragma unroll
    for (int nt = 0; nt < 8; nt++)
#pragma unroll
        for (int e = 0; e < 4; e++) o[nt][e] = 0.0f;
    float m[2] = {-1e30f, -1e30f}, l[2] = {0.0f, 0.0f};
    uint32_t qh[4][4], ql[4][4];

    const int ktmax = 2 * qtb + 1;
    const int rmin = q0 + w * 16;        // first row this warp owns
    const int rmax = rmin + 15;          // last row this warp owns

    for (int kt = 0; kt <= ktmax; kt++) {
        const int buf = kt & 1;
        if (kt < ktmax) {
            loadKV(kt + 1, buf ^ 1);
            cp_commit();
            cp_wait<1>();
        } else {
            cp_wait<0>();
        }
        __syncthreads();

        if (kt == 0) {
#pragma unroll
            for (int ks = 0; ks < 4; ks++) {
                uint32_t off = (uint32_t)((w * 16 + (lane & 15)) * FAP
                                          + ks * 16 + (lane >> 4) * 8) * 2;
                ldsm_x4(qh[ks], smem_u32(sQh) + off);
                ldsm_x4(ql[ks], smem_u32(sQl) + off);
            }
        }

        const int k0 = kt * 64;
        if (k0 <= rmax) {
            __nv_bfloat16* Kh = sKV + buf * 4 * FA_KV_ELEMS;
            __nv_bfloat16* Kl = Kh + FA_KV_ELEMS;
            __nv_bfloat16* Vh = Kh + 2 * FA_KV_ELEMS;
            __nv_bfloat16* Vl = Kh + 3 * FA_KV_ELEMS;

            float s[8][4];
#pragma unroll
            for (int nt = 0; nt < 8; nt++)
#pragma unroll
                for (int e = 0; e < 4; e++) s[nt][e] = 0.0f;

            // S = Q K^T  (bf16x3)
#pragma unroll
            for (int ks = 0; ks < 4; ks++) {
#pragma unroll
                for (int p = 0; p < 4; p++) {
                    uint32_t roff = (uint32_t)((p * 16 + ((lane >> 4) << 3) + (lane & 7)) * FAP
                                               + ks * 16 + (((lane >> 3) & 1) << 3)) * 2;
                    uint32_t bh4[4], bl4[4];
                    ldsm_x4(bh4, smem_u32(Kh) + roff);
                    ldsm_x4(bl4, smem_u32(Kl) + roff);
                    uint32_t b0h[2] = {bh4[0], bh4[1]}, b1h[2] = {bh4[2], bh4[3]};
                    uint32_t b0l[2] = {bl4[0], bl4[1]}, b1l[2] = {bl4[2], bl4[3]};
                    mma16816(s[2 * p],     qh[ks], b0h);
                    mma16816(s[2 * p],     qh[ks], b0l);
                    mma16816(s[2 * p],     ql[ks], b0h);
                    mma16816(s[2 * p + 1], qh[ks], b1h);
                    mma16816(s[2 * p + 1], qh[ks], b1l);
                    mma16816(s[2 * p + 1], ql[ks], b1h);
                }
            }

            // scale into log2 domain
            const float SC = 0.18033688011112042f;  // 0.125 * log2(e)
#pragma unroll
            for (int nt = 0; nt < 8; nt++)
#pragma unroll
                for (int e = 0; e < 4; e++) s[nt][e] *= SC;

            // causal mask: needed whenever tile's last column exceeds warp's first row
            if (k0 + 63 > rmin) {
#pragma unroll
                for (int nt = 0; nt < 8; nt++)
#pragma unroll
                    for (int e = 0; e < 4; e++) {
                        int col = k0 + nt * 8 + 2 * (lane & 3) + (e & 1);
                        int row = rmin + (lane >> 2) + (e >> 1) * 8;
                        if (col > row) s[nt][e] = -1e30f;
                    }
            }

            // online softmax (quad lanes share a row)
#pragma unroll
            for (int half = 0; half < 2; half++) {
                float tm = -1e30f;
#pragma unroll
                for (int nt = 0; nt < 8; nt++)
                    tm = fmaxf(tm, fmaxf(s[nt][2 * half], s[nt][2 * half + 1]));
                tm = fmaxf(tm, __shfl_xor_sync(0xffffffffu, tm, 1));
                tm = fmaxf(tm, __shfl_xor_sync(0xffffffffu, tm, 2));
                float mn = fmaxf(m[half], tm);
                float alpha = exp2f(m[half] - mn);
                m[half] = mn;
                float ps = 0.0f;
#pragma unroll
                for (int nt = 0; nt < 8; nt++) {
                    s[nt][2 * half]     = exp2f(s[nt][2 * half] - mn);
                    s[nt][2 * half + 1] = exp2f(s[nt][2 * half + 1] - mn);
                    ps += s[nt][2 * half] + s[nt][2 * half + 1];
                }
                l[half] = l[half] * alpha + ps;
#pragma unroll
                for (int nt = 0; nt < 8; nt++) {
                    o[nt][2 * half]     *= alpha;
                    o[nt][2 * half + 1] *= alpha;
                }
            }

            // O += P V   (P split hi/lo in regs; V bf16 hi/lo)
#pragma unroll
            for (int ks = 0; ks < 4; ks++) {
                uint32_t pah[4], pal[4];
                packsplit(s[2 * ks][0],     s[2 * ks][1],     pah[0], pal[0]);
                packsplit(s[2 * ks][2],     s[2 * ks][3],     pah[1], pal[1]);
                packsplit(s[2 * ks + 1][0], s[2 * ks + 1][1], pah[2], pal[2]);
                packsplit(s[2 * ks + 1][2], s[2 * ks + 1][3], pah[3], pal[3]);
#pragma unroll
                for (int p = 0; p < 4; p++) {
                    uint32_t roff = (uint32_t)((ks * 16 + (lane & 15)) * FAP
                                               + p * 16 + (lane >> 4) * 8) * 2;
                    uint32_t vh4[4], vl4[4];
                    ldsm_x4t(vh4, smem_u32(Vh) + roff);
                    ldsm_x4t(vl4, smem_u32(Vl) + roff);
                    uint32_t b0h[2] = {vh4[0], vh4[1]}, b1h[2] = {vh4[2], vh4[3]};
                    uint32_t b0l[2] = {vl4[0], vl4[1]}, b1l[2] = {vl4[2], vl4[3]};
                    mma16816(o[2 * p],     pah, b0h);
                    mma16816(o[2 * p],     pah, b0l);
                    mma16816(o[2 * p],     pal, b0h);
                    mma16816(o[2 * p + 1], pah, b1h);
                    mma16816(o[2 * p + 1], pah, b1l);
                    mma16816(o[2 * p + 1], pal, b1h);
                }
            }
        }
        __syncthreads();
    }

    // final normalize + split-write
    float linv[2];
#pragma unroll
    for (int half = 0; half < 2; half++) {
        float lv = l[half];
        lv += __shfl_xor_sync(0xffffffffu, lv, 1);
        lv += __shfl_xor_sync(0xffffffffu, lv, 2);
        linv[half] = 1.0f / lv;
    }
#pragma unroll
    for (int nt = 0; nt < 8; nt++) {
#pragma unroll
        for (int half = 0; half < 2; half++) {
            int rowg = q0 + w * 16 + (lane >> 2) + half * 8;
            int colg = h * HD + nt * 8 + 2 * (lane & 3);
            float f0 = o[nt][2 * half]     * linv[half];
            float f1 = o[nt][2 * half + 1] * linv[half];
            uint32_t hv, lv;
            packsplit(f0, f1, hv, lv);
            size_t off = (size_t)(b * TSEQ + rowg) * CDIM + colg;
            *(uint32_t*)(outh + off) = hv;
            *(uint32_t*)(outl + off) = lv;
        }
    }
}

// ---------------- launch ----------------
extern "C" void kernel_launch(void* const* d_in, const int* in_sizes, int n_in,
                              void* d_out, int out_size)
{
    const float* x       = (const float*)d_in[0];
    const float* ln1_w   = (const float*)d_in[1];
    const float* ln1_b   = (const float*)d_in[2];
    const float* attn_w  = (const float*)d_in[3];
    const float* attn_b  = (const float*)d_in[4];
    const float* proj_w  = (const float*)d_in[5];
    const float* proj_b  = (const float*)d_in[6];
    const float* ln2_w   = (const float*)d_in[7];
    const float* ln2_b   = (const float*)d_in[8];
    const float* fc_w    = (const float*)d_in[9];
    const float* fc_b    = (const float*)d_in[10];
    const float* mproj_w = (const float*)d_in[11];
    const float* mproj_b = (const float*)d_in[12];
    float* out = (float*)d_out;

    __nv_bfloat16 *lnh, *lnl, *qkvh, *qkvl, *atth, *attl, *fch, *fcl, *wh, *wl;
    float *x1;
    cudaGetSymbolAddress((void**)&lnh,  g_lnh);
    cudaGetSymbolAddress((void**)&lnl,  g_lnl);
    cudaGetSymbolAddress((void**)&qkvh, g_qkvh);
    cudaGetSymbolAddress((void**)&qkvl, g_qkvl);
    cudaGetSymbolAddress((void**)&atth, g_atth);
    cudaGetSymbolAddress((void**)&attl, g_attl);
    cudaGetSymbolAddress((void**)&x1,   g_x1);
    cudaGetSymbolAddress((void**)&fch,  g_fch);
    cudaGetSymbolAddress((void**)&fcl,  g_fcl);
    cudaGetSymbolAddress((void**)&wh,   g_wh);
    cudaGetSymbolAddress((void**)&wl,   g_wl);

    __nv_bfloat16 *wqkvh = wh,                 *wqkvl = wl;
    __nv_bfloat16 *wprojh = wh + W_QKV_N,      *wprojl = wl + W_QKV_N;
    __nv_bfloat16 *wfch = wprojh + W_PROJ_N,   *wfcl = wprojl + W_PROJ_N;
    __nv_bfloat16 *wmph = wfch + W_FC_N,       *wmpl = wfcl + W_FC_N;

    cudaFuncSetAttribute(flash_attn_tc,
                         cudaFuncAttributeMaxDynamicSharedMemorySize, FA2_SMEM);
    cudaFuncSetAttribute((const void*)hgemm<0, false, true>,
                         cudaFuncAttributeMaxDynamicSharedMemorySize, GEMM_SMEM_BYTES);
    cudaFuncSetAttribute((const void*)hgemm<2, true, false>,
                         cudaFuncAttributeMaxDynamicSharedMemorySize, GEMM_SMEM_BYTES);
    cudaFuncSetAttribute((const void*)hgemm<1, false, true>,
                         cudaFuncAttributeMaxDynamicSharedMemorySize, GEMM_SMEM_BYTES);

    // 0) split weights to bf16 hi/lo
    split4_kernel<<<(W_QKV_N / 4 + 255) / 256, 256>>>(
        (const float4*)attn_w, (__nv_bfloat162*)wqkvh, (__nv_bfloat162*)wqkvl, W_QKV_N / 4);
    split4_kernel<<<(W_PROJ_N / 4 + 255) / 256, 256>>>(
        (const float4*)proj_w, (__nv_bfloat162*)wprojh, (__nv_bfloat162*)wprojl, W_PROJ_N / 4);
    split4_kernel<<<(W_FC_N / 4 + 255) / 256, 256>>>(
        (const float4*)fc_w, (__nv_bfloat162*)wfch, (__nv_bfloat162*)wfcl, W_FC_N / 4);
    split4_kernel<<<(W_MP_N / 4 + 255) / 256, 256>>>(
        (const float4*)mproj_w, (__nv_bfloat162*)wmph, (__nv_bfloat162*)wmpl, W_MP_N / 4);

    // 1) ln1 -> bf16 hi/lo
    ln_split_kernel<<<MROWS, 256>>>(x, ln1_w, ln1_b, lnh, lnl);
    // 2) qkv = ln1 @ W_attn + b   [8192, 2304] -> split bf16
    hgemm<0, false, true><<<dim3(2304 / 128, MROWS / 256), 256, GEMM_SMEM_BYTES>>>(
        MROWS, 2304, CDIM, lnh, lnl, wqkvh, wqkvl, attn_b, nullptr,
        nullptr, qkvh, qkvl);
    // 3) attention (tensor cores) -> bf16 hi/lo
    flash_attn_tc<<<dim3(TSEQ / 128, NHEAD, NBATCH), 256, FA2_SMEM>>>(
        qkvh, qkvl, atth, attl);
    // 4) x1 = x + att @ W_proj + b   (fp32)
    hgemm<2, true, false><<<dim3(CDIM / 128, MROWS / 256), 256, GEMM_SMEM_BYTES>>>(
        MROWS, CDIM, CDIM, atth, attl, wprojh, wprojl, proj_b, x,
        x1, nullptr, nullptr);
    // 5) ln2 -> bf16 hi/lo
    ln_split_kernel<<<MROWS, 256>>>(x1, ln2_w, ln2_b, lnh, lnl);
    // 6) fc = gelu(ln2 @ W_fc + b)   [8192, 3072] -> bf16 hi/lo
    hgemm<1, false, true><<<dim3(3072 / 128, MROWS / 256), 256, GEMM_SMEM_BYTES>>>(
        MROWS, 3072, CDIM, lnh, lnl, wfch, wfcl, fc_b, nullptr,
        nullptr, fch, fcl);
    // 7) out = x1 + fc @ W_mproj + b   (fp32)
    hgemm<2, true, false><<<dim3(CDIM / 128, MROWS / 256), 256, GEMM_SMEM_BYTES>>>(
        MROWS, CDIM, 4 * CDIM, fch, fcl, wmph, wmpl, mproj_b, x1,
        out, nullptr, nullptr);
}

// round 7
// speedup vs baseline: 1.0267x; 1.0267x over previous
#include <cuda_runtime.h>
#include <cuda_bf16.h>
#include <math.h>
#include <stdint.h>

#define MROWS 8192           // B*T = 4*2048
#define CDIM  768
#define TSEQ  2048
#define NBATCH 4
#define NHEAD 12
#define HD    64

// ---------------- scratch (no allocations allowed) ----------------
__device__ __nv_bfloat16 g_lnh[(size_t)MROWS * CDIM];
__device__ __nv_bfloat16 g_lnl[(size_t)MROWS * CDIM];
__device__ __nv_bfloat16 g_qkvh[(size_t)MROWS * 3 * CDIM];
__device__ __nv_bfloat16 g_qkvl[(size_t)MROWS * 3 * CDIM];
__device__ __nv_bfloat16 g_atth[(size_t)MROWS * CDIM];
__device__ __nv_bfloat16 g_attl[(size_t)MROWS * CDIM];
__device__ float         g_x1 [(size_t)MROWS * CDIM];
__device__ __nv_bfloat16 g_fch[(size_t)MROWS * 4 * CDIM];
__device__ __nv_bfloat16 g_fcl[(size_t)MROWS * 4 * CDIM];

#define W_QKV_N (768*2304)
#define W_PROJ_N (768*768)
#define W_FC_N (768*3072)
#define W_MP_N (3072*768)
__device__ __nv_bfloat16 g_wh[W_QKV_N + W_PROJ_N + W_FC_N + W_MP_N];
__device__ __nv_bfloat16 g_wl[W_QKV_N + W_PROJ_N + W_FC_N + W_MP_N];

// ---------------- helpers ----------------
__device__ __forceinline__ float warp_sum(float v) {
#pragma unroll
    for (int m = 16; m; m >>= 1) v += __shfl_xor_sync(0xffffffffu, v, m);
    return v;
}

__device__ __forceinline__ float gelu_tanh(float x) {
    const float c = 0.7978845608028654f;  // sqrt(2/pi)
    float x3 = x * x * x;
    return 0.5f * x * (1.0f + tanhf(c * (x + 0.044715f * x3)));
}

__device__ __forceinline__ uint32_t smem_u32(const void* p) {
    return (uint32_t)__cvta_generic_to_shared(p);
}

__device__ __forceinline__ void cp16(uint32_t dst, const void* src) {
    asm volatile("cp.async.cg.shared.global [%0], [%1], 16;\n" :: "r"(dst), "l"(src));
}
__device__ __forceinline__ void cp_commit() { asm volatile("cp.async.commit_group;\n"); }
template<int N> __device__ __forceinline__ void cp_wait() {
    asm volatile("cp.async.wait_group %0;\n" :: "n"(N));
}

__device__ __forceinline__ void ldsm_x4(uint32_t (&r)[4], uint32_t addr) {
    asm volatile("ldmatrix.sync.aligned.m8n8.x4.shared.b16 {%0,%1,%2,%3}, [%4];"
        : "=r"(r[0]), "=r"(r[1]), "=r"(r[2]), "=r"(r[3]) : "r"(addr));
}
__device__ __forceinline__ void ldsm_x4t(uint32_t (&r)[4], uint32_t addr) {
    asm volatile("ldmatrix.sync.aligned.m8n8.x4.trans.shared.b16 {%0,%1,%2,%3}, [%4];"
        : "=r"(r[0]), "=r"(r[1]), "=r"(r[2]), "=r"(r[3]) : "r"(addr));
}
__device__ __forceinline__ void mma16816(float (&d)[4], const uint32_t (&a)[4],
                                         const uint32_t (&b)[2]) {
    asm volatile(
        "mma.sync.aligned.m16n8k16.row.col.f32.bf16.bf16.f32 "
        "{%0,%1,%2,%3},{%4,%5,%6,%7},{%8,%9},{%0,%1,%2,%3};"
        : "+f"(d[0]), "+f"(d[1]), "+f"(d[2]), "+f"(d[3])
        : "r"(a[0]), "r"(a[1]), "r"(a[2]), "r"(a[3]), "r"(b[0]), "r"(b[1]));
}

__device__ __forceinline__ void split_bf16(float v, __nv_bfloat16& h, __nv_bfloat16& l) {
    h = __float2bfloat16(v);
    l = __float2bfloat16(v - __bfloat162float(h));
}

__device__ __forceinline__ void packsplit(float x0, float x1, uint32_t& h, uint32_t& l) {
    __nv_bfloat16 h0, h1, l0, l1;
    split_bf16(x0, h0, l0);
    split_bf16(x1, h1, l1);
    __nv_bfloat162 hv(h0, h1), lv(l0, l1);
    h = *(uint32_t*)&hv;
    l = *(uint32_t*)&lv;
}

// ---------------- weight split: f32 -> bf16 hi/lo --------------------
__global__ __launch_bounds__(256) void split4_kernel(
    const float4* __restrict__ s, __nv_bfloat162* __restrict__ h,
    __nv_bfloat162* __restrict__ l, int n4)
{
    int i = blockIdx.x * 256 + threadIdx.x;
    if (i >= n4) return;
    float4 v = s[i];
    __nv_bfloat16 h0, h1, h2, h3, l0, l1, l2, l3;
    split_bf16(v.x, h0, l0); split_bf16(v.y, h1, l1);
    split_bf16(v.z, h2, l2); split_bf16(v.w, h3, l3);
    h[2 * i]     = __nv_bfloat162(h0, h1);
    h[2 * i + 1] = __nv_bfloat162(h2, h3);
    l[2 * i]     = __nv_bfloat162(l0, l1);
    l[2 * i + 1] = __nv_bfloat162(l2, l3);
}

// ---------------- LayerNorm (row = 768, ddof=1) -> bf16 hi/lo --------
__global__ __launch_bounds__(256) void ln_split_kernel(
    const float* __restrict__ x, const float* __restrict__ w,
    const float* __restrict__ b, __nv_bfloat16* __restrict__ yh,
    __nv_bfloat16* __restrict__ yl)
{
    const int row = blockIdx.x;
    const float* xr = x + (size_t)row * CDIM;
    const int t = threadIdx.x;

    float v0 = xr[t], v1 = xr[t + 256], v2 = xr[t + 512];
    float s  = v0 + v1 + v2;
    float s2 = v0 * v0 + v1 * v1 + v2 * v2;

    __shared__ float sh[2][8];
    s = warp_sum(s); s2 = warp_sum(s2);
    int wid = t >> 5, lane = t & 31;
    if (lane == 0) { sh[0][wid] = s; sh[1][wid] = s2; }
    __syncthreads();
    if (wid == 0) {
        float a = (lane < 8) ? sh[0][lane] : 0.0f;
        float c = (lane < 8) ? sh[1][lane] : 0.0f;
        a = warp_sum(a); c = warp_sum(c);
        if (lane == 0) { sh[0][0] = a; sh[1][0] = c; }
    }
    __syncthreads();
    s = sh[0][0]; s2 = sh[1][0];

    float mean = s * (1.0f / (float)CDIM);
    float var  = (s2 - (float)CDIM * mean * mean) * (1.0f / (float)(CDIM - 1));
    float rstd = rsqrtf(var + 1e-5f);

    size_t base = (size_t)row * CDIM;
#pragma unroll
    for (int j = 0; j < 3; j++) {
        int c = t + j * 256;
        float v = (j == 0 ? v0 : (j == 1 ? v1 : v2));
        float y = (v - mean) * rstd * w[c] + b[c];
        __nv_bfloat16 hh, ll;
        split_bf16(y, hh, ll);
        yh[base + c] = hh;
        yl[base + c] = ll;
    }
}

// ---------------- bf16x3 tensor-core GEMM, 128x128x32 ----------------
// 3-pass MMA issue: same-accumulator reuse distance 16 (was 1).
#define GEMM_SMEM_ELEMS (2*(2*128*40) + 2*(2*32*136))
#define GEMM_SMEM_BYTES (GEMM_SMEM_ELEMS * 2)

template<int EPI, bool STOREF, bool SPLIT>
__global__ __launch_bounds__(256, 1) void hgemm(
    int M, int N, int K,
    const __nv_bfloat16* __restrict__ Ah, const __nv_bfloat16* __restrict__ Al,
    const __nv_bfloat16* __restrict__ Bh, const __nv_bfloat16* __restrict__ Bl,
    const float* __restrict__ bias, const float* __restrict__ Res,
    float* __restrict__ C, __nv_bfloat16* __restrict__ Ch,
    __nv_bfloat16* __restrict__ Cl)
{
    extern __shared__ __nv_bfloat16 sm[];
    __nv_bfloat16* sAh = sm;                    // [2][128][40]
    __nv_bfloat16* sAl = sAh + 2 * 128 * 40;
    __nv_bfloat16* sBh = sAl + 2 * 128 * 40;    // [2][32][136]
    __nv_bfloat16* sBl = sBh + 2 * 32 * 136;
    const uint32_t uAh = smem_u32(sAh), uAl = smem_u32(sAl);
    const uint32_t uBh = smem_u32(sBh), uBl = smem_u32(sBl);

    const int tid  = threadIdx.x;
    const int warp = tid >> 5, lane = tid & 31;
    const int wr = warp >> 1, wc = warp & 1;
    const int bm = blockIdx.y * 128, bn = blockIdx.x * 128;

    float acc[2][8][4];
#pragma unroll
    for (int i = 0; i < 2; i++)
#pragma unroll
        for (int j = 0; j < 8; j++)
#pragma unroll
            for (int k = 0; k < 4; k++) acc[i][j][k] = 0.0f;

    auto load_tile = [&](int kt, int buf) {
#pragma unroll
        for (int i = 0; i < 2; i++) {
            int id = tid + i * 256;
            int r = id >> 2, c = id & 3;
            uint32_t off = (uint32_t)((buf * 128 + r) * 40 + c * 8) * 2;
            size_t g = (size_t)(bm + r) * K + kt * 32 + c * 8;
            cp16(uAh + off, Ah + g);
            cp16(uAl + off, Al + g);
        }
#pragma unroll
        for (int i = 0; i < 2; i++) {
            int id = tid + i * 256;
            int r = id >> 4, c = id & 15;
            uint32_t off = (uint32_t)((buf * 32 + r) * 136 + c * 8) * 2;
            size_t g = (size_t)(kt * 32 + r) * N + bn + c * 8;
            cp16(uBh + off, Bh + g);
            cp16(uBl + off, Bl + g);
        }
    };

    const int KT = K >> 5;
    load_tile(0, 0);
    cp_commit();

    for (int kt = 0; kt < KT; ++kt) {
        const int buf = kt & 1;
        if (kt + 1 < KT) {
            load_tile(kt + 1, buf ^ 1);
            cp_commit();
            cp_wait<1>();
        } else {
            cp_wait<0>();
        }
        __syncthreads();

#pragma unroll
        for (int ks = 0; ks < 2; ++ks) {
            uint32_t ah[2][4], al[2][4], bh[8][2], bl[8][2];
#pragma unroll
            for (int ti = 0; ti < 2; ++ti) {
                int r = wr * 32 + ti * 16 + (lane & 15);
                int col = ks * 16 + (lane >> 4) * 8;
                uint32_t off = (uint32_t)((buf * 128 + r) * 40 + col) * 2;
                ldsm_x4(ah[ti], uAh + off);
                ldsm_x4(al[ti], uAl + off);
            }
#pragma unroll
            for (int p = 0; p < 4; ++p) {
                int kr = ks * 16 + (lane & 15);
                int col = wc * 64 + p * 16 + (lane >> 4) * 8;
                uint32_t off = (uint32_t)((buf * 32 + kr) * 136 + col) * 2;
                uint32_t r4[4];
                ldsm_x4t(r4, uBh + off);
                bh[2 * p][0] = r4[0]; bh[2 * p][1] = r4[1];
                bh[2 * p + 1][0] = r4[2]; bh[2 * p + 1][1] = r4[3];
                ldsm_x4t(r4, uBl + off);
                bl[2 * p][0] = r4[0]; bl[2 * p][1] = r4[1];
                bl[2 * p + 1][0] = r4[2]; bl[2 * p + 1][1] = r4[3];
            }
            // pass 1: Ah * Bh  (16 independent MMAs)
#pragma unroll
            for (int ti = 0; ti < 2; ++ti)
#pragma unroll
                for (int nj = 0; nj < 8; ++nj)
                    mma16816(acc[ti][nj], ah[ti], bh[nj]);
            // pass 2: Ah * Bl
#pragma unroll
            for (int ti = 0; ti < 2; ++ti)
#pragma unroll
                for (int nj = 0; nj < 8; ++nj)
                    mma16816(acc[ti][nj], ah[ti], bl[nj]);
            // pass 3: Al * Bh
#pragma unroll
            for (int ti = 0; ti < 2; ++ti)
#pragma unroll
                for (int nj = 0; nj < 8; ++nj)
                    mma16816(acc[ti][nj], al[ti], bh[nj]);
        }
        __syncthreads();
    }

    const int row_base = bm + wr * 32;
    const int col_base = bn + wc * 64;
#pragma unroll
    for (int ti = 0; ti < 2; ++ti) {
        int r0 = row_base + ti * 16 + (lane >> 2);
#pragma unroll
        for (int nj = 0; nj < 8; ++nj) {
            int col = col_base + nj * 8 + (lane & 3) * 2;
            float b0 = bias[col], b1 = bias[col + 1];
            float v00 = acc[ti][nj][0] + b0, v01 = acc[ti][nj][1] + b1;
            float v10 = acc[ti][nj][2] + b0, v11 = acc[ti][nj][3] + b1;
            if (EPI == 1) {
                v00 = gelu_tanh(v00); v01 = gelu_tanh(v01);
                v10 = gelu_tanh(v10); v11 = gelu_tanh(v11);
            }
            size_t o0 = (size_t)r0 * N + col;
            size_t o1 = (size_t)(r0 + 8) * N + col;
            if (EPI == 2) {
                v00 += Res[o0]; v01 += Res[o0 + 1];
                v10 += Res[o1]; v11 += Res[o1 + 1];
            }
            if (STOREF) {
                float2 f0; f0.x = v00; f0.y = v01;
                float2 f1; f1.x = v10; f1.y = v11;
                *(float2*)(C + o0) = f0;
                *(float2*)(C + o1) = f1;
            }
            if (SPLIT) {
                uint32_t h0, l0, h1, l1;
                packsplit(v00, v01, h0, l0);
                packsplit(v10, v11, h1, l1);
                *(uint32_t*)(Ch + o0) = h0;
                *(uint32_t*)(Ch + o1) = h1;
                *(uint32_t*)(Cl + o0) = l0;
                *(uint32_t*)(Cl + o1) = l1;
            }
        }
    }
}

// ---------------- Flash attention, bf16x3 tensor cores ----------------
// Br=128 (8 warps), Bc=64; 3-pass MMA issue in QK^T and PV.
#define FAP 72
#define FA_Q_ELEMS (128 * FAP)
#define FA_KV_ELEMS (64 * FAP)
#define FA2_SMEM ((2 * FA_Q_ELEMS + 8 * FA_KV_ELEMS) * 2)

__global__ __launch_bounds__(256) void flash_attn_tc(
    const __nv_bfloat16* __restrict__ qh_g, const __nv_bfloat16* __restrict__ ql_g,
    __nv_bfloat16* __restrict__ outh, __nv_bfloat16* __restrict__ outl)
{
    extern __shared__ __nv_bfloat16 sb[];
    __nv_bfloat16* sQh = sb;                      // [128][72]
    __nv_bfloat16* sQl = sQh + FA_Q_ELEMS;
    __nv_bfloat16* sKV = sQl + FA_Q_ELEMS;        // [2][Kh,Kl,Vh,Vl][64][72]

    const int tid = threadIdx.x, lane = tid & 31, w = tid >> 5;
    const int b = blockIdx.z, h = blockIdx.y, qtb = blockIdx.x;
    const int q0 = qtb * 128;
    const size_t rs = 3 * CDIM;
    const __nv_bfloat16* baseh = qh_g + (size_t)b * TSEQ * rs + h * HD;
    const __nv_bfloat16* basel = ql_g + (size_t)b * TSEQ * rs + h * HD;

#pragma unroll
    for (int i = 0; i < 4; i++) {
        int id = tid + i * 256;
        int r = id >> 3, c8 = id & 7;
        size_t g = (size_t)(q0 + r) * rs + c8 * 8;
        cp16(smem_u32(sQh + r * FAP + c8 * 8), baseh + g);
        cp16(smem_u32(sQl + r * FAP + c8 * 8), basel + g);
    }

    auto loadKV = [&](int kt, int buf) {
        const int k0 = kt * 64;
        __nv_bfloat16* d = sKV + buf * 4 * FA_KV_ELEMS;
        const __nv_bfloat16* srcs[4] = { baseh + CDIM, basel + CDIM,
                                         baseh + 2 * CDIM, basel + 2 * CDIM };
#pragma unroll
        for (int a = 0; a < 4; a++) {
#pragma unroll
            for (int i = 0; i < 2; i++) {
                int id = tid + i * 256;
                int r = id >> 3, c8 = id & 7;
                cp16(smem_u32(d + a * FA_KV_ELEMS + r * FAP + c8 * 8),
                     srcs[a] + (size_t)(k0 + r) * rs + c8 * 8);
            }
        }
    };

    loadKV(0, 0);
    cp_commit();

    float o[8][4];
#pragma unroll
    for (int nt = 0; nt < 8; nt++)
#pragma unroll
        for (int e = 0; e < 4; e++) o[nt][e] = 0.0f;
    float m[2] = {-1e30f, -1e30f}, l[2] = {0.0f, 0.0f};
    uint32_t qh[4][4], ql[4][4];

    const int ktmax = 2 * qtb + 1;
    const int rmin = q0 + w * 16;
    const int rmax = rmin + 15;

    for (int kt = 0; kt <= ktmax; kt++) {
        const int buf = kt & 1;
        if (kt < ktmax) {
            loadKV(kt + 1, buf ^ 1);
            cp_commit();
            cp_wait<1>();
        } else {
            cp_wait<0>();
        }
        __syncthreads();

        if (kt == 0) {
#pragma unroll
            for (int ks = 0; ks < 4; ks++) {
                uint32_t off = (uint32_t)((w * 16 + (lane & 15)) * FAP
                                          + ks * 16 + (lane >> 4) * 8) * 2;
                ldsm_x4(qh[ks], smem_u32(sQh) + off);
                ldsm_x4(ql[ks], smem_u32(sQl) + off);
            }
        }

        const int k0 = kt * 64;
        if (k0 <= rmax) {
            __nv_bfloat16* Kh = sKV + buf * 4 * FA_KV_ELEMS;
            __nv_bfloat16* Kl = Kh + FA_KV_ELEMS;
            __nv_bfloat16* Vh = Kh + 2 * FA_KV_ELEMS;
            __nv_bfloat16* Vl = Kh + 3 * FA_KV_ELEMS;

            float s[8][4];
#pragma unroll
            for (int nt = 0; nt < 8; nt++)
#pragma unroll
                for (int e = 0; e < 4; e++) s[nt][e] = 0.0f;

            // S = Q K^T  (bf16x3, 3-pass issue)
#pragma unroll
            for (int ks = 0; ks < 4; ks++) {
                uint32_t kbh[8][2], kbl[8][2];
#pragma unroll
                for (int p = 0; p < 4; p++) {
                    uint32_t roff = (uint32_t)((p * 16 + ((lane >> 4) << 3) + (lane & 7)) * FAP
                                               + ks * 16 + (((lane >> 3) & 1) << 3)) * 2;
                    uint32_t r4[4];
                    ldsm_x4(r4, smem_u32(Kh) + roff);
                    kbh[2 * p][0] = r4[0]; kbh[2 * p][1] = r4[1];
                    kbh[2 * p + 1][0] = r4[2]; kbh[2 * p + 1][1] = r4[3];
                    ldsm_x4(r4, smem_u32(Kl) + roff);
                    kbl[2 * p][0] = r4[0]; kbl[2 * p][1] = r4[1];
                    kbl[2 * p + 1][0] = r4[2]; kbl[2 * p + 1][1] = r4[3];
                }
#pragma unroll
                for (int t = 0; t < 8; t++) mma16816(s[t], qh[ks], kbh[t]);
#pragma unroll
                for (int t = 0; t < 8; t++) mma16816(s[t], qh[ks], kbl[t]);
#pragma unroll
                for (int t = 0; t < 8; t++) mma16816(s[t], ql[ks], kbh[t]);
            }

            const float SC = 0.18033688011112042f;  // 0.125 * log2(e)
#pragma unroll
            for (int nt = 0; nt < 8; nt++)
#pragma unroll
                for (int e = 0; e < 4; e++) s[nt][e] *= SC;

            if (k0 + 63 > rmin) {
#pragma unroll
                for (int nt = 0; nt < 8; nt++)
#pragma unroll
                    for (int e = 0; e < 4; e++) {
                        int col = k0 + nt * 8 + 2 * (lane & 3) + (e & 1);
                        int rr = rmin + (lane >> 2) + (e >> 1) * 8;
                        if (col > rr) s[nt][e] = -1e30f;
                    }
            }

#pragma unroll
            for (int half = 0; half < 2; half++) {
                float tm = -1e30f;
#pragma unroll
                for (int nt = 0; nt < 8; nt++)
                    tm = fmaxf(tm, fmaxf(s[nt][2 * half], s[nt][2 * half + 1]));
                tm = fmaxf(tm, __shfl_xor_sync(0xffffffffu, tm, 1));
                tm = fmaxf(tm, __shfl_xor_sync(0xffffffffu, tm, 2));
                float mn = fmaxf(m[half], tm);
                float alpha = exp2f(m[half] - mn);
                m[half] = mn;
                float ps = 0.0f;
#pragma unroll
                for (int nt = 0; nt < 8; nt++) {
                    s[nt][2 * half]     = exp2f(s[nt][2 * half] - mn);
                    s[nt][2 * half + 1] = exp2f(s[nt][2 * half + 1] - mn);
                    ps += s[nt][2 * half] + s[nt][2 * half + 1];
                }
                l[half] = l[half] * alpha + ps;
#pragma unroll
                for (int nt = 0; nt < 8; nt++) {
                    o[nt][2 * half]     *= alpha;
                    o[nt][2 * half + 1] *= alpha;
                }
            }

            // O += P V   (3-pass issue)
#pragma unroll
            for (int ks = 0; ks < 4; ks++) {
                uint32_t pah[4], pal[4];
                packsplit(s[2 * ks][0],     s[2 * ks][1],     pah[0], pal[0]);
                packsplit(s[2 * ks][2],     s[2 * ks][3],     pah[1], pal[1]);
                packsplit(s[2 * ks + 1][0], s[2 * ks + 1][1], pah[2], pal[2]);
                packsplit(s[2 * ks + 1][2], s[2 * ks + 1][3], pah[3], pal[3]);
                uint32_t vbh[8][2], vbl[8][2];
#pragma unroll
                for (int p = 0; p < 4; p++) {
                    uint32_t roff = (uint32_t)((ks * 16 + (lane & 15)) * FAP
                                               + p * 16 + (lane >> 4) * 8) * 2;
                    uint32_t r4[4];
                    ldsm_x4t(r4, smem_u32(Vh) + roff);
                    vbh[2 * p][0] = r4[0]; vbh[2 * p][1] = r4[1];
                    vbh[2 * p + 1][0] = r4[2]; vbh[2 * p + 1][1] = r4[3];
                    ldsm_x4t(r4, smem_u32(Vl) + roff);
                    vbl[2 * p][0] = r4[0]; vbl[2 * p][1] = r4[1];
                    vbl[2 * p + 1][0] = r4[2]; vbl[2 * p + 1][1] = r4[3];
                }
#pragma unroll
                for (int t = 0; t < 8; t++) mma16816(o[t], pah, vbh[t]);
#pragma unroll
                for (int t = 0; t < 8; t++) mma16816(o[t], pah, vbl[t]);
#pragma unroll
                for (int t = 0; t < 8; t++) mma16816(o[t], pal, vbh[t]);
            }
        }
        __syncthreads();
    }

    float linv[2];
#pragma unroll
    for (int half = 0; half < 2; half++) {
        float lv = l[half];
        lv += __shfl_xor_sync(0xffffffffu, lv, 1);
        lv += __shfl_xor_sync(0xffffffffu, lv, 2);
        linv[half] = 1.0f / lv;
    }
#pragma unroll
    for (int nt = 0; nt < 8; nt++) {
#pragma unroll
        for (int half = 0; half < 2; half++) {
            int rowg = q0 + w * 16 + (lane >> 2) + half * 8;
            int colg = h * HD + nt * 8 + 2 * (lane & 3);
            float f0 = o[nt][2 * half]     * linv[half];
            float f1 = o[nt][2 * half + 1] * linv[half];
            uint32_t hv, lv;
            packsplit(f0, f1, hv, lv);
            size_t off = (size_t)(b * TSEQ + rowg) * CDIM + colg;
            *(uint32_t*)(outh + off) = hv;
            *(uint32_t*)(outl + off) = lv;
        }
    }
}

// ---------------- launch ----------------
extern "C" void kernel_launch(void* const* d_in, const int* in_sizes, int n_in,
                              void* d_out, int out_size)
{
    const float* x       = (const float*)d_in[0];
    const float* ln1_w   = (const float*)d_in[1];
    const float* ln1_b   = (const float*)d_in[2];
    const float* attn_w  = (const float*)d_in[3];
    const float* attn_b  = (const float*)d_in[4];
    const float* proj_w  = (const float*)d_in[5];
    const float* proj_b  = (const float*)d_in[6];
    const float* ln2_w   = (const float*)d_in[7];
    const float* ln2_b   = (const float*)d_in[8];
    const float* fc_w    = (const float*)d_in[9];
    const float* fc_b    = (const float*)d_in[10];
    const float* mproj_w = (const float*)d_in[11];
    const float* mproj_b = (const float*)d_in[12];
    float* out = (float*)d_out;

    __nv_bfloat16 *lnh, *lnl, *qkvh, *qkvl, *atth, *attl, *fch, *fcl, *wh, *wl;
    float *x1;
    cudaGetSymbolAddress((void**)&lnh,  g_lnh);
    cudaGetSymbolAddress((void**)&lnl,  g_lnl);
    cudaGetSymbolAddress((void**)&qkvh, g_qkvh);
    cudaGetSymbolAddress((void**)&qkvl, g_qkvl);
    cudaGetSymbolAddress((void**)&atth, g_atth);
    cudaGetSymbolAddress((void**)&attl, g_attl);
    cudaGetSymbolAddress((void**)&x1,   g_x1);
    cudaGetSymbolAddress((void**)&fch,  g_fch);
    cudaGetSymbolAddress((void**)&fcl,  g_fcl);
    cudaGetSymbolAddress((void**)&wh,   g_wh);
    cudaGetSymbolAddress((void**)&wl,   g_wl);

    __nv_bfloat16 *wqkvh = wh,                 *wqkvl = wl;
    __nv_bfloat16 *wprojh = wh + W_QKV_N,      *wprojl = wl + W_QKV_N;
    __nv_bfloat16 *wfch = wprojh + W_PROJ_N,   *wfcl = wprojl + W_PROJ_N;
    __nv_bfloat16 *wmph = wfch + W_FC_N,       *wmpl = wfcl + W_FC_N;

    cudaFuncSetAttribute(flash_attn_tc,
                         cudaFuncAttributeMaxDynamicSharedMemorySize, FA2_SMEM);
    cudaFuncSetAttribute((const void*)hgemm<0, false, true>,
                         cudaFuncAttributeMaxDynamicSharedMemorySize, GEMM_SMEM_BYTES);
    cudaFuncSetAttribute((const void*)hgemm<2, true, false>,
                         cudaFuncAttributeMaxDynamicSharedMemorySize, GEMM_SMEM_BYTES);
    cudaFuncSetAttribute((const void*)hgemm<1, false, true>,
                         cudaFuncAttributeMaxDynamicSharedMemorySize, GEMM_SMEM_BYTES);

    // 0) split weights to bf16 hi/lo
    split4_kernel<<<(W_QKV_N / 4 + 255) / 256, 256>>>(
        (const float4*)attn_w, (__nv_bfloat162*)wqkvh, (__nv_bfloat162*)wqkvl, W_QKV_N / 4);
    split4_kernel<<<(W_PROJ_N / 4 + 255) / 256, 256>>>(
        (const float4*)proj_w, (__nv_bfloat162*)wprojh, (__nv_bfloat162*)wprojl, W_PROJ_N / 4);
    split4_kernel<<<(W_FC_N / 4 + 255) / 256, 256>>>(
        (const float4*)fc_w, (__nv_bfloat162*)wfch, (__nv_bfloat162*)wfcl, W_FC_N / 4);
    split4_kernel<<<(W_MP_N / 4 + 255) / 256, 256>>>(
        (const float4*)mproj_w, (__nv_bfloat162*)wmph, (__nv_bfloat162*)wmpl, W_MP_N / 4);

    // 1) ln1 -> bf16 hi/lo
    ln_split_kernel<<<MROWS, 256>>>(x, ln1_w, ln1_b, lnh, lnl);
    // 2) qkv = ln1 @ W_attn + b   [8192, 2304] -> split bf16
    hgemm<0, false, true><<<dim3(2304 / 128, MROWS / 128), 256, GEMM_SMEM_BYTES>>>(
        MROWS, 2304, CDIM, lnh, lnl, wqkvh, wqkvl, attn_b, nullptr,
        nullptr, qkvh, qkvl);
    // 3) attention (tensor cores) -> bf16 hi/lo
    flash_attn_tc<<<dim3(TSEQ / 128, NHEAD, NBATCH), 256, FA2_SMEM>>>(
        qkvh, qkvl, atth, attl);
    // 4) x1 = x + att @ W_proj + b   (fp32)
    hgemm<2, true, false><<<dim3(CDIM / 128, MROWS / 128), 256, GEMM_SMEM_BYTES>>>(
        MROWS, CDIM, CDIM, atth, attl, wprojh, wprojl, proj_b, x,
        x1, nullptr, nullptr);
    // 5) ln2 -> bf16 hi/lo
    ln_split_kernel<<<MROWS, 256>>>(x1, ln2_w, ln2_b, lnh, lnl);
    // 6) fc = gelu(ln2 @ W_fc + b)   [8192, 3072] -> bf16 hi/lo
    hgemm<1, false, true><<<dim3(3072 / 128, MROWS / 128), 256, GEMM_SMEM_BYTES>>>(
        MROWS, 3072, CDIM, lnh, lnl, wfch, wfcl, fc_b, nullptr,
        nullptr, fch, fcl);
    // 7) out = x1 + fc @ W_mproj + b   (fp32)
    hgemm<2, true, false><<<dim3(CDIM / 128, MROWS / 128), 256, GEMM_SMEM_BYTES>>>(
        MROWS, CDIM, 4 * CDIM, fch, fcl, wmph, wmpl, mproj_b, x1,
        out, nullptr, nullptr);
}

// round 8
// speedup vs baseline: 2.7012x; 2.6309x over previous
#include <cuda_runtime.h>
#include <cuda_fp16.h>
#include <math.h>
#include <stdint.h>

#define MROWS 8192           // B*T = 4*2048
#define CDIM  768
#define TSEQ  2048
#define NBATCH 4
#define NHEAD 12
#define HD    64

// ---------------- scratch (no allocations allowed) ----------------
__device__ __half g_ln [(size_t)MROWS * CDIM];
__device__ __half g_qkv[(size_t)MROWS * 3 * CDIM];
__device__ __half g_att[(size_t)MROWS * CDIM];
__device__ float  g_x1 [(size_t)MROWS * CDIM];
__device__ __half g_fc [(size_t)MROWS * 4 * CDIM];

#define W_QKV_N (768*2304)
#define W_PROJ_N (768*768)
#define W_FC_N (768*3072)
#define W_MP_N (3072*768)
__device__ __half g_w[W_QKV_N + W_PROJ_N + W_FC_N + W_MP_N];

// ---------------- helpers ----------------
__device__ __forceinline__ float warp_sum(float v) {
#pragma unroll
    for (int m = 16; m; m >>= 1) v += __shfl_xor_sync(0xffffffffu, v, m);
    return v;
}

__device__ __forceinline__ float gelu_tanh(float x) {
    const float c = 0.7978845608028654f;  // sqrt(2/pi)
    float x3 = x * x * x;
    return 0.5f * x * (1.0f + tanhf(c * (x + 0.044715f * x3)));
}

__device__ __forceinline__ uint32_t smem_u32(const void* p) {
    return (uint32_t)__cvta_generic_to_shared(p);
}

__device__ __forceinline__ void cp16(uint32_t dst, const void* src) {
    asm volatile("cp.async.cg.shared.global [%0], [%1], 16;\n" :: "r"(dst), "l"(src));
}
__device__ __forceinline__ void cp_commit() { asm volatile("cp.async.commit_group;\n"); }
template<int N> __device__ __forceinline__ void cp_wait() {
    asm volatile("cp.async.wait_group %0;\n" :: "n"(N));
}

__device__ __forceinline__ void ldsm_x4(uint32_t (&r)[4], uint32_t addr) {
    asm volatile("ldmatrix.sync.aligned.m8n8.x4.shared.b16 {%0,%1,%2,%3}, [%4];"
        : "=r"(r[0]), "=r"(r[1]), "=r"(r[2]), "=r"(r[3]) : "r"(addr));
}
__device__ __forceinline__ void ldsm_x4t(uint32_t (&r)[4], uint32_t addr) {
    asm volatile("ldmatrix.sync.aligned.m8n8.x4.trans.shared.b16 {%0,%1,%2,%3}, [%4];"
        : "=r"(r[0]), "=r"(r[1]), "=r"(r[2]), "=r"(r[3]) : "r"(addr));
}
__device__ __forceinline__ void mma16816(float (&d)[4], const uint32_t (&a)[4],
                                         const uint32_t (&b)[2]) {
    asm volatile(
        "mma.sync.aligned.m16n8k16.row.col.f32.f16.f16.f32 "
        "{%0,%1,%2,%3},{%4,%5,%6,%7},{%8,%9},{%0,%1,%2,%3};"
        : "+f"(d[0]), "+f"(d[1]), "+f"(d[2]), "+f"(d[3])
        : "r"(a[0]), "r"(a[1]), "r"(a[2]), "r"(a[3]), "r"(b[0]), "r"(b[1]));
}

__device__ __forceinline__ uint32_t packh(float a, float b) {
    __half2 h = __floats2half2_rn(a, b);
    return *(uint32_t*)&h;
}

// ---------------- weight convert f32 -> fp16 --------------------
__global__ __launch_bounds__(256) void cvt4_kernel(
    const float4* __restrict__ s, uint32_t* __restrict__ h, int n4)
{
    int i = blockIdx.x * 256 + threadIdx.x;
    if (i >= n4) return;
    float4 v = s[i];
    h[2 * i]     = packh(v.x, v.y);
    h[2 * i + 1] = packh(v.z, v.w);
}

// ---------------- LayerNorm (row = 768, ddof=1) -> fp16 --------
__global__ __launch_bounds__(256) void ln_kernel(
    const float* __restrict__ x, const float* __restrict__ w,
    const float* __restrict__ b, __half* __restrict__ y)
{
    const int row = blockIdx.x;
    const float* xr = x + (size_t)row * CDIM;
    const int t = threadIdx.x;

    float v0 = xr[t], v1 = xr[t + 256], v2 = xr[t + 512];
    float s  = v0 + v1 + v2;
    float s2 = v0 * v0 + v1 * v1 + v2 * v2;

    __shared__ float sh[2][8];
    s = warp_sum(s); s2 = warp_sum(s2);
    int wid = t >> 5, lane = t & 31;
    if (lane == 0) { sh[0][wid] = s; sh[1][wid] = s2; }
    __syncthreads();
    if (wid == 0) {
        float a = (lane < 8) ? sh[0][lane] : 0.0f;
        float c = (lane < 8) ? sh[1][lane] : 0.0f;
        a = warp_sum(a); c = warp_sum(c);
        if (lane == 0) { sh[0][0] = a; sh[1][0] = c; }
    }
    __syncthreads();
    s = sh[0][0]; s2 = sh[1][0];

    float mean = s * (1.0f / (float)CDIM);
    float var  = (s2 - (float)CDIM * mean * mean) * (1.0f / (float)(CDIM - 1));
    float rstd = rsqrtf(var + 1e-5f);

    size_t base = (size_t)row * CDIM;
#pragma unroll
    for (int j = 0; j < 3; j++) {
        int c = t + j * 256;
        float v = (j == 0 ? v0 : (j == 1 ? v1 : v2));
        y[base + c] = __float2half_rn((v - mean) * rstd * w[c] + b[c]);
    }
}

// ---------------- fp16 tensor-core GEMM, 128x128x32 ----------------
// EPI: 0=+bias, 1=gelu(+bias), 2=+bias+residual.
// STOREF: fp32 out.  STOREH: fp16 out (next GEMM input).
#define GEMM_SMEM_ELEMS ((2*128*40) + (2*32*136))
#define GEMM_SMEM_BYTES (GEMM_SMEM_ELEMS * 2)

template<int EPI, bool STOREF, bool STOREH>
__global__ __launch_bounds__(256, 2) void hgemm(
    int M, int N, int K,
    const __half* __restrict__ A, const __half* __restrict__ B,
    const float* __restrict__ bias, const float* __restrict__ Res,
    float* __restrict__ C, __half* __restrict__ Ch)
{
    extern __shared__ __half sm[];
    __half* sA = sm;                    // [2][128][40]
    __half* sB = sA + 2 * 128 * 40;     // [2][32][136]
    const uint32_t uA = smem_u32(sA), uB = smem_u32(sB);

    const int tid  = threadIdx.x;
    const int warp = tid >> 5, lane = tid & 31;
    const int wr = warp >> 1, wc = warp & 1;
    const int bm = blockIdx.y * 128, bn = blockIdx.x * 128;

    float acc[2][8][4];
#pragma unroll
    for (int i = 0; i < 2; i++)
#pragma unroll
        for (int j = 0; j < 8; j++)
#pragma unroll
            for (int k = 0; k < 4; k++) acc[i][j][k] = 0.0f;

    auto load_tile = [&](int kt, int buf) {
#pragma unroll
        for (int i = 0; i < 2; i++) {
            int id = tid + i * 256;
            int r = id >> 2, c = id & 3;
            uint32_t off = (uint32_t)((buf * 128 + r) * 40 + c * 8) * 2;
            cp16(uA + off, A + (size_t)(bm + r) * K + kt * 32 + c * 8);
        }
#pragma unroll
        for (int i = 0; i < 2; i++) {
            int id = tid + i * 256;
            int r = id >> 4, c = id & 15;
            uint32_t off = (uint32_t)((buf * 32 + r) * 136 + c * 8) * 2;
            cp16(uB + off, B + (size_t)(kt * 32 + r) * N + bn + c * 8);
        }
    };

    const int KT = K >> 5;
    load_tile(0, 0);
    cp_commit();

    for (int kt = 0; kt < KT; ++kt) {
        const int buf = kt & 1;
        if (kt + 1 < KT) {
            load_tile(kt + 1, buf ^ 1);
            cp_commit();
            cp_wait<1>();
        } else {
            cp_wait<0>();
        }
        __syncthreads();

#pragma unroll
        for (int ks = 0; ks < 2; ++ks) {
            uint32_t a[2][4], b[8][2];
#pragma unroll
            for (int ti = 0; ti < 2; ++ti) {
                int r = wr * 32 + ti * 16 + (lane & 15);
                int col = ks * 16 + (lane >> 4) * 8;
                ldsm_x4(a[ti], uA + (uint32_t)((buf * 128 + r) * 40 + col) * 2);
            }
#pragma unroll
            for (int p = 0; p < 4; ++p) {
                int kr = ks * 16 + (lane & 15);
                int col = wc * 64 + p * 16 + (lane >> 4) * 8;
                uint32_t r4[4];
                ldsm_x4t(r4, uB + (uint32_t)((buf * 32 + kr) * 136 + col) * 2);
                b[2 * p][0] = r4[0]; b[2 * p][1] = r4[1];
                b[2 * p + 1][0] = r4[2]; b[2 * p + 1][1] = r4[3];
            }
#pragma unroll
            for (int ti = 0; ti < 2; ++ti)
#pragma unroll
                for (int nj = 0; nj < 8; ++nj)
                    mma16816(acc[ti][nj], a[ti], b[nj]);
        }
        __syncthreads();
    }

    const int row_base = bm + wr * 32;
    const int col_base = bn + wc * 64;
#pragma unroll
    for (int ti = 0; ti < 2; ++ti) {
        int r0 = row_base + ti * 16 + (lane >> 2);
#pragma unroll
        for (int nj = 0; nj < 8; ++nj) {
            int col = col_base + nj * 8 + (lane & 3) * 2;
            float b0 = bias[col], b1 = bias[col + 1];
            float v00 = acc[ti][nj][0] + b0, v01 = acc[ti][nj][1] + b1;
            float v10 = acc[ti][nj][2] + b0, v11 = acc[ti][nj][3] + b1;
            if (EPI == 1) {
                v00 = gelu_tanh(v00); v01 = gelu_tanh(v01);
                v10 = gelu_tanh(v10); v11 = gelu_tanh(v11);
            }
            size_t o0 = (size_t)r0 * N + col;
            size_t o1 = (size_t)(r0 + 8) * N + col;
            if (EPI == 2) {
                v00 += Res[o0]; v01 += Res[o0 + 1];
                v10 += Res[o1]; v11 += Res[o1 + 1];
            }
            if (STOREF) {
                float2 f0; f0.x = v00; f0.y = v01;
                float2 f1; f1.x = v10; f1.y = v11;
                *(float2*)(C + o0) = f0;
                *(float2*)(C + o1) = f1;
            }
            if (STOREH) {
                *(uint32_t*)(Ch + o0) = packh(v00, v01);
                *(uint32_t*)(Ch + o1) = packh(v10, v11);
            }
        }
    }
}

// ---------------- Flash attention, fp16 tensor cores ----------------
// Br=128 (8 warps), Bc=64. qkv fp16 [row][3C].
#define FAP 72
#define FA_Q_ELEMS (128 * FAP)
#define FA_KV_ELEMS (64 * FAP)
#define FA2_SMEM ((FA_Q_ELEMS + 4 * FA_KV_ELEMS) * 2)

__global__ __launch_bounds__(256, 2) void flash_attn_tc(
    const __half* __restrict__ qkv, __half* __restrict__ outp)
{
    extern __shared__ __half sb[];
    __half* sQ = sb;                       // [128][72]
    __half* sKV = sQ + FA_Q_ELEMS;         // [2][K,V][64][72]

    const int tid = threadIdx.x, lane = tid & 31, w = tid >> 5;
    const int b = blockIdx.z, h = blockIdx.y, qtb = blockIdx.x;
    const int q0 = qtb * 128;
    const size_t rs = 3 * CDIM;
    const __half* base = qkv + (size_t)b * TSEQ * rs + h * HD;

#pragma unroll
    for (int i = 0; i < 4; i++) {
        int id = tid + i * 256;
        int r = id >> 3, c8 = id & 7;
        cp16(smem_u32(sQ + r * FAP + c8 * 8), base + (size_t)(q0 + r) * rs + c8 * 8);
    }

    auto loadKV = [&](int kt, int buf) {
        const int k0 = kt * 64;
        __half* d = sKV + buf * 2 * FA_KV_ELEMS;
        const __half* srcs[2] = { base + CDIM, base + 2 * CDIM };
#pragma unroll
        for (int a = 0; a < 2; a++) {
#pragma unroll
            for (int i = 0; i < 2; i++) {
                int id = tid + i * 256;
                int r = id >> 3, c8 = id & 7;
                cp16(smem_u32(d + a * FA_KV_ELEMS + r * FAP + c8 * 8),
                     srcs[a] + (size_t)(k0 + r) * rs + c8 * 8);
            }
        }
    };

    loadKV(0, 0);
    cp_commit();

    float o[8][4];
#pragma unroll
    for (int nt = 0; nt < 8; nt++)
#pragma unroll
        for (int e = 0; e < 4; e++) o[nt][e] = 0.0f;
    float m[2] = {-1e30f, -1e30f}, l[2] = {0.0f, 0.0f};
    uint32_t qf[4][4];

    const int ktmax = 2 * qtb + 1;
    const int rmin = q0 + w * 16;
    const int rmax = rmin + 15;

    for (int kt = 0; kt <= ktmax; kt++) {
        const int buf = kt & 1;
        if (kt < ktmax) {
            loadKV(kt + 1, buf ^ 1);
            cp_commit();
            cp_wait<1>();
        } else {
            cp_wait<0>();
        }
        __syncthreads();

        if (kt == 0) {
#pragma unroll
            for (int ks = 0; ks < 4; ks++) {
                uint32_t off = (uint32_t)((w * 16 + (lane & 15)) * FAP
                                          + ks * 16 + (lane >> 4) * 8) * 2;
                ldsm_x4(qf[ks], smem_u32(sQ) + off);
            }
        }

        const int k0 = kt * 64;
        if (k0 <= rmax) {
            __half* Kt = sKV + buf * 2 * FA_KV_ELEMS;
            __half* Vt = Kt + FA_KV_ELEMS;

            float s[8][4];
#pragma unroll
            for (int nt = 0; nt < 8; nt++)
#pragma unroll
                for (int e = 0; e < 4; e++) s[nt][e] = 0.0f;

            // S = Q K^T
#pragma unroll
            for (int ks = 0; ks < 4; ks++) {
                uint32_t kb[8][2];
#pragma unroll
                for (int p = 0; p < 4; p++) {
                    uint32_t roff = (uint32_t)((p * 16 + ((lane >> 4) << 3) + (lane & 7)) * FAP
                                               + ks * 16 + (((lane >> 3) & 1) << 3)) * 2;
                    uint32_t r4[4];
                    ldsm_x4(r4, smem_u32(Kt) + roff);
                    kb[2 * p][0] = r4[0]; kb[2 * p][1] = r4[1];
                    kb[2 * p + 1][0] = r4[2]; kb[2 * p + 1][1] = r4[3];
                }
#pragma unroll
                for (int t = 0; t < 8; t++) mma16816(s[t], qf[ks], kb[t]);
            }

            const float SC = 0.18033688011112042f;  // 0.125 * log2(e)
#pragma unroll
            for (int nt = 0; nt < 8; nt++)
#pragma unroll
                for (int e = 0; e < 4; e++) s[nt][e] *= SC;

            if (k0 + 63 > rmin) {
#pragma unroll
                for (int nt = 0; nt < 8; nt++)
#pragma unroll
                    for (int e = 0; e < 4; e++) {
                        int col = k0 + nt * 8 + 2 * (lane & 3) + (e & 1);
                        int rr = rmin + (lane >> 2) + (e >> 1) * 8;
                        if (col > rr) s[nt][e] = -1e30f;
                    }
            }

#pragma unroll
            for (int half = 0; half < 2; half++) {
                float tm = -1e30f;
#pragma unroll
                for (int nt = 0; nt < 8; nt++)
                    tm = fmaxf(tm, fmaxf(s[nt][2 * half], s[nt][2 * half + 1]));
                tm = fmaxf(tm, __shfl_xor_sync(0xffffffffu, tm, 1));
                tm = fmaxf(tm, __shfl_xor_sync(0xffffffffu, tm, 2));
                float mn = fmaxf(m[half], tm);
                float alpha = exp2f(m[half] - mn);
                m[half] = mn;
                float ps = 0.0f;
#pragma unroll
                for (int nt = 0; nt < 8; nt++) {
                    s[nt][2 * half]     = exp2f(s[nt][2 * half] - mn);
                    s[nt][2 * half + 1] = exp2f(s[nt][2 * half + 1] - mn);
                    ps += s[nt][2 * half] + s[nt][2 * half + 1];
                }
                l[half] = l[half] * alpha + ps;
#pragma unroll
                for (int nt = 0; nt < 8; nt++) {
                    o[nt][2 * half]     *= alpha;
                    o[nt][2 * half + 1] *= alpha;
                }
            }

            // O += P V
#pragma unroll
            for (int ks = 0; ks < 4; ks++) {
                uint32_t pa[4];
                pa[0] = packh(s[2 * ks][0],     s[2 * ks][1]);
                pa[1] = packh(s[2 * ks][2],     s[2 * ks][3]);
                pa[2] = packh(s[2 * ks + 1][0], s[2 * ks + 1][1]);
                pa[3] = packh(s[2 * ks + 1][2], s[2 * ks + 1][3]);
                uint32_t vb[8][2];
#pragma unroll
                for (int p = 0; p < 4; p++) {
                    uint32_t roff = (uint32_t)((ks * 16 + (lane & 15)) * FAP
                                               + p * 16 + (lane >> 4) * 8) * 2;
                    uint32_t r4[4];
                    ldsm_x4t(r4, smem_u32(Vt) + roff);
                    vb[2 * p][0] = r4[0]; vb[2 * p][1] = r4[1];
                    vb[2 * p + 1][0] = r4[2]; vb[2 * p + 1][1] = r4[3];
                }
#pragma unroll
                for (int t = 0; t < 8; t++) mma16816(o[t], pa, vb[t]);
            }
        }
        __syncthreads();
    }

    float linv[2];
#pragma unroll
    for (int half = 0; half < 2; half++) {
        float lv = l[half];
        lv += __shfl_xor_sync(0xffffffffu, lv, 1);
        lv += __shfl_xor_sync(0xffffffffu, lv, 2);
        linv[half] = 1.0f / lv;
    }
#pragma unroll
    for (int nt = 0; nt < 8; nt++) {
#pragma unroll
        for (int half = 0; half < 2; half++) {
            int rowg = q0 + w * 16 + (lane >> 2) + half * 8;
            int colg = h * HD + nt * 8 + 2 * (lane & 3);
            float f0 = o[nt][2 * half]     * linv[half];
            float f1 = o[nt][2 * half + 1] * linv[half];
            size_t off = (size_t)(b * TSEQ + rowg) * CDIM + colg;
            *(uint32_t*)(outp + off) = packh(f0, f1);
        }
    }
}

// ---------------- launch ----------------
extern "C" void kernel_launch(void* const* d_in, const int* in_sizes, int n_in,
                              void* d_out, int out_size)
{
    const float* x       = (const float*)d_in[0];
    const float* ln1_w   = (const float*)d_in[1];
    const float* ln1_b   = (const float*)d_in[2];
    const float* attn_w  = (const float*)d_in[3];
    const float* attn_b  = (const float*)d_in[4];
    const float* proj_w  = (const float*)d_in[5];
    const float* proj_b  = (const float*)d_in[6];
    const float* ln2_w   = (const float*)d_in[7];
    const float* ln2_b   = (const float*)d_in[8];
    const float* fc_w    = (const float*)d_in[9];
    const float* fc_b    = (const float*)d_in[10];
    const float* mproj_w = (const float*)d_in[11];
    const float* mproj_b = (const float*)d_in[12];
    float* out = (float*)d_out;

    __half *ln, *qkv, *att, *fc, *wv;
    float *x1;
    cudaGetSymbolAddress((void**)&ln,  g_ln);
    cudaGetSymbolAddress((void**)&qkv, g_qkv);
    cudaGetSymbolAddress((void**)&att, g_att);
    cudaGetSymbolAddress((void**)&x1,  g_x1);
    cudaGetSymbolAddress((void**)&fc,  g_fc);
    cudaGetSymbolAddress((void**)&wv,  g_w);

    __half *wqkv = wv;
    __half *wproj = wv + W_QKV_N;
    __half *wfc = wproj + W_PROJ_N;
    __half *wmp = wfc + W_FC_N;

    cudaFuncSetAttribute(flash_attn_tc,
                         cudaFuncAttributeMaxDynamicSharedMemorySize, FA2_SMEM);
    cudaFuncSetAttribute((const void*)hgemm<0, false, true>,
                         cudaFuncAttributeMaxDynamicSharedMemorySize, GEMM_SMEM_BYTES);
    cudaFuncSetAttribute((const void*)hgemm<2, true, false>,
                         cudaFuncAttributeMaxDynamicSharedMemorySize, GEMM_SMEM_BYTES);
    cudaFuncSetAttribute((const void*)hgemm<1, false, true>,
                         cudaFuncAttributeMaxDynamicSharedMemorySize, GEMM_SMEM_BYTES);

    // 0) convert weights to fp16
    cvt4_kernel<<<(W_QKV_N / 4 + 255) / 256, 256>>>(
        (const float4*)attn_w, (uint32_t*)wqkv, W_QKV_N / 4);
    cvt4_kernel<<<(W_PROJ_N / 4 + 255) / 256, 256>>>(
        (const float4*)proj_w, (uint32_t*)wproj, W_PROJ_N / 4);
    cvt4_kernel<<<(W_FC_N / 4 + 255) / 256, 256>>>(
        (const float4*)fc_w, (uint32_t*)wfc, W_FC_N / 4);
    cvt4_kernel<<<(W_MP_N / 4 + 255) / 256, 256>>>(
        (const float4*)mproj_w, (uint32_t*)wmp, W_MP_N / 4);

    // 1) ln1 -> fp16
    ln_kernel<<<MROWS, 256>>>(x, ln1_w, ln1_b, ln);
    // 2) qkv = ln1 @ W_attn + b   [8192, 2304] -> fp16
    hgemm<0, false, true><<<dim3(2304 / 128, MROWS / 128), 256, GEMM_SMEM_BYTES>>>(
        MROWS, 2304, CDIM, ln, wqkv, attn_b, nullptr, nullptr, qkv);
    // 3) attention -> fp16
    flash_attn_tc<<<dim3(TSEQ / 128, NHEAD, NBATCH), 256, FA2_SMEM>>>(qkv, att);
    // 4) x1 = x + att @ W_proj + b   (fp32)
    hgemm<2, true, false><<<dim3(CDIM / 128, MROWS / 128), 256, GEMM_SMEM_BYTES>>>(
        MROWS, CDIM, CDIM, att, wproj, proj_b, x, x1, nullptr);
    // 5) ln2 -> fp16
    ln_kernel<<<MROWS, 256>>>(x1, ln2_w, ln2_b, ln);
    // 6) fc = gelu(ln2 @ W_fc + b)   [8192, 3072] -> fp16
    hgemm<1, false, true><<<dim3(3072 / 128, MROWS / 128), 256, GEMM_SMEM_BYTES>>>(
        MROWS, 3072, CDIM, ln, wfc, fc_b, nullptr, nullptr, fc);
    // 7) out = x1 + fc @ W_mproj + b   (fp32)
    hgemm<2, true, false><<<dim3(CDIM / 128, MROWS / 128), 256, GEMM_SMEM_BYTES>>>(
        MROWS, CDIM, 4 * CDIM, fc, wmp, mproj_b, x1, out, nullptr);
}

// round 9
// speedup vs baseline: 2.7787x; 1.0287x over previous
#include <cuda_runtime.h>
#include <cuda_fp16.h>
#include <math.h>
#include <stdint.h>

#define MROWS 8192           // B*T = 4*2048
#define CDIM  768
#define TSEQ  2048
#define NBATCH 4
#define NHEAD 12
#define HD    64

// ---------------- scratch (no allocations allowed) ----------------
__device__ __half g_ln [(size_t)MROWS * CDIM];
__device__ __half g_qkv[(size_t)MROWS * 3 * CDIM];
__device__ __half g_att[(size_t)MROWS * CDIM];
__device__ float  g_x1 [(size_t)MROWS * CDIM];
__device__ __half g_fc [(size_t)MROWS * 4 * CDIM];

#define W_QKV_N (768*2304)
#define W_PROJ_N (768*768)
#define W_FC_N (768*3072)
#define W_MP_N (3072*768)
__device__ __half g_w[W_QKV_N + W_PROJ_N + W_FC_N + W_MP_N];

// ---------------- helpers ----------------
__device__ __forceinline__ float warp_sum(float v) {
#pragma unroll
    for (int m = 16; m; m >>= 1) v += __shfl_xor_sync(0xffffffffu, v, m);
    return v;
}

__device__ __forceinline__ float fast_ex2(float x) {
    float y;
    asm("ex2.approx.ftz.f32 %0, %1;" : "=f"(y) : "f"(x));
    return y;
}
__device__ __forceinline__ float fast_rcp(float x) {
    float y;
    asm("rcp.approx.ftz.f32 %0, %1;" : "=f"(y) : "f"(x));
    return y;
}

__device__ __forceinline__ float gelu_tanh(float x) {
    // tanh(u) = 1 - 2/(exp2(2u*log2e)+1)
    const float c = 0.7978845608028654f;  // sqrt(2/pi)
    float u = c * (x + 0.044715f * x * x * x);
    float t = fast_ex2(2.885390081777927f * u);   // exp(2u)
    float th = 1.0f - 2.0f * fast_rcp(t + 1.0f);
    return 0.5f * x * (1.0f + th);
}

__device__ __forceinline__ uint32_t smem_u32(const void* p) {
    return (uint32_t)__cvta_generic_to_shared(p);
}

__device__ __forceinline__ void cp16(uint32_t dst, const void* src) {
    asm volatile("cp.async.cg.shared.global [%0], [%1], 16;\n" :: "r"(dst), "l"(src));
}
__device__ __forceinline__ void cp_commit() { asm volatile("cp.async.commit_group;\n"); }
template<int N> __device__ __forceinline__ void cp_wait() {
    asm volatile("cp.async.wait_group %0;\n" :: "n"(N));
}

__device__ __forceinline__ void ldsm_x4(uint32_t (&r)[4], uint32_t addr) {
    asm volatile("ldmatrix.sync.aligned.m8n8.x4.shared.b16 {%0,%1,%2,%3}, [%4];"
        : "=r"(r[0]), "=r"(r[1]), "=r"(r[2]), "=r"(r[3]) : "r"(addr));
}
__device__ __forceinline__ void ldsm_x4t(uint32_t (&r)[4], uint32_t addr) {
    asm volatile("ldmatrix.sync.aligned.m8n8.x4.trans.shared.b16 {%0,%1,%2,%3}, [%4];"
        : "=r"(r[0]), "=r"(r[1]), "=r"(r[2]), "=r"(r[3]) : "r"(addr));
}
__device__ __forceinline__ void mma16816(float (&d)[4], const uint32_t (&a)[4],
                                         const uint32_t (&b)[2]) {
    asm volatile(
        "mma.sync.aligned.m16n8k16.row.col.f32.f16.f16.f32 "
        "{%0,%1,%2,%3},{%4,%5,%6,%7},{%8,%9},{%0,%1,%2,%3};"
        : "+f"(d[0]), "+f"(d[1]), "+f"(d[2]), "+f"(d[3])
        : "r"(a[0]), "r"(a[1]), "r"(a[2]), "r"(a[3]), "r"(b[0]), "r"(b[1]));
}

__device__ __forceinline__ uint32_t packh(float a, float b) {
    __half2 h = __floats2half2_rn(a, b);
    return *(uint32_t*)&h;
}

// ---------------- fused weight convert f32 -> fp16 (one launch) ------
#define N4_QKV (W_QKV_N / 4)
#define N4_PROJ (W_PROJ_N / 4)
#define N4_FC (W_FC_N / 4)
#define N4_MP (W_MP_N / 4)
#define N4_TOTAL (N4_QKV + N4_PROJ + N4_FC + N4_MP)

__global__ __launch_bounds__(256) void cvt_all_kernel(
    const float4* __restrict__ w0, const float4* __restrict__ w1,
    const float4* __restrict__ w2, const float4* __restrict__ w3,
    uint32_t* __restrict__ h)
{
    int i = blockIdx.x * 256 + threadIdx.x;
    if (i >= N4_TOTAL) return;
    const float4* src;
    int j = i;
    if (j < N4_QKV) { src = w0; }
    else if ((j -= N4_QKV) < N4_PROJ) { src = w1; }
    else if ((j -= N4_PROJ) < N4_FC) { src = w2; }
    else { j -= N4_FC; src = w3; }
    float4 v = src[j];
    h[2 * i]     = packh(v.x, v.y);
    h[2 * i + 1] = packh(v.z, v.w);
}

// ---------------- LayerNorm (row = 768, ddof=1) -> fp16 --------
__global__ __launch_bounds__(256) void ln_kernel(
    const float* __restrict__ x, const float* __restrict__ w,
    const float* __restrict__ b, __half* __restrict__ y)
{
    const int row = blockIdx.x;
    const float* xr = x + (size_t)row * CDIM;
    const int t = threadIdx.x;

    float v0 = xr[t], v1 = xr[t + 256], v2 = xr[t + 512];
    float s  = v0 + v1 + v2;
    float s2 = v0 * v0 + v1 * v1 + v2 * v2;

    __shared__ float sh[2][8];
    s = warp_sum(s); s2 = warp_sum(s2);
    int wid = t >> 5, lane = t & 31;
    if (lane == 0) { sh[0][wid] = s; sh[1][wid] = s2; }
    __syncthreads();
    if (wid == 0) {
        float a = (lane < 8) ? sh[0][lane] : 0.0f;
        float c = (lane < 8) ? sh[1][lane] : 0.0f;
        a = warp_sum(a); c = warp_sum(c);
        if (lane == 0) { sh[0][0] = a; sh[1][0] = c; }
    }
    __syncthreads();
    s = sh[0][0]; s2 = sh[1][0];

    float mean = s * (1.0f / (float)CDIM);
    float var  = (s2 - (float)CDIM * mean * mean) * (1.0f / (float)(CDIM - 1));
    float rstd = rsqrtf(var + 1e-5f);

    size_t base = (size_t)row * CDIM;
#pragma unroll
    for (int j = 0; j < 3; j++) {
        int c = t + j * 256;
        float v = (j == 0 ? v0 : (j == 1 ? v1 : v2));
        y[base + c] = __float2half_rn((v - mean) * rstd * w[c] + b[c]);
    }
}

// ---------------- fp16 tensor-core GEMM, 128x128x32 ----------------
#define GEMM_SMEM_ELEMS ((2*128*40) + (2*32*136))
#define GEMM_SMEM_BYTES (GEMM_SMEM_ELEMS * 2)

template<int EPI, bool STOREF, bool STOREH>
__global__ __launch_bounds__(256, 2) void hgemm(
    int M, int N, int K,
    const __half* __restrict__ A, const __half* __restrict__ B,
    const float* __restrict__ bias, const float* __restrict__ Res,
    float* __restrict__ C, __half* __restrict__ Ch)
{
    extern __shared__ __half sm[];
    __half* sA = sm;                    // [2][128][40]
    __half* sB = sA + 2 * 128 * 40;     // [2][32][136]
    const uint32_t uA = smem_u32(sA), uB = smem_u32(sB);

    const int tid  = threadIdx.x;
    const int warp = tid >> 5, lane = tid & 31;
    const int wr = warp >> 1, wc = warp & 1;
    const int bm = blockIdx.y * 128, bn = blockIdx.x * 128;

    float acc[2][8][4];
#pragma unroll
    for (int i = 0; i < 2; i++)
#pragma unroll
        for (int j = 0; j < 8; j++)
#pragma unroll
            for (int k = 0; k < 4; k++) acc[i][j][k] = 0.0f;

    auto load_tile = [&](int kt, int buf) {
#pragma unroll
        for (int i = 0; i < 2; i++) {
            int id = tid + i * 256;
            int r = id >> 2, c = id & 3;
            uint32_t off = (uint32_t)((buf * 128 + r) * 40 + c * 8) * 2;
            cp16(uA + off, A + (size_t)(bm + r) * K + kt * 32 + c * 8);
        }
#pragma unroll
        for (int i = 0; i < 2; i++) {
            int id = tid + i * 256;
            int r = id >> 4, c = id & 15;
            uint32_t off = (uint32_t)((buf * 32 + r) * 136 + c * 8) * 2;
            cp16(uB + off, B + (size_t)(kt * 32 + r) * N + bn + c * 8);
        }
    };

    const int KT = K >> 5;
    load_tile(0, 0);
    cp_commit();

    for (int kt = 0; kt < KT; ++kt) {
        const int buf = kt & 1;
        if (kt + 1 < KT) {
            load_tile(kt + 1, buf ^ 1);
            cp_commit();
            cp_wait<1>();
        } else {
            cp_wait<0>();
        }
        __syncthreads();

#pragma unroll
        for (int ks = 0; ks < 2; ++ks) {
            uint32_t a[2][4], b[8][2];
#pragma unroll
            for (int ti = 0; ti < 2; ++ti) {
                int r = wr * 32 + ti * 16 + (lane & 15);
                int col = ks * 16 + (lane >> 4) * 8;
                ldsm_x4(a[ti], uA + (uint32_t)((buf * 128 + r) * 40 + col) * 2);
            }
#pragma unroll
            for (int p = 0; p < 4; ++p) {
                int kr = ks * 16 + (lane & 15);
                int col = wc * 64 + p * 16 + (lane >> 4) * 8;
                uint32_t r4[4];
                ldsm_x4t(r4, uB + (uint32_t)((buf * 32 + kr) * 136 + col) * 2);
                b[2 * p][0] = r4[0]; b[2 * p][1] = r4[1];
                b[2 * p + 1][0] = r4[2]; b[2 * p + 1][1] = r4[3];
            }
#pragma unroll
            for (int ti = 0; ti < 2; ++ti)
#pragma unroll
                for (int nj = 0; nj < 8; ++nj)
                    mma16816(acc[ti][nj], a[ti], b[nj]);
        }
        __syncthreads();
    }

    const int row_base = bm + wr * 32;
    const int col_base = bn + wc * 64;
#pragma unroll
    for (int ti = 0; ti < 2; ++ti) {
        int r0 = row_base + ti * 16 + (lane >> 2);
#pragma unroll
        for (int nj = 0; nj < 8; ++nj) {
            int col = col_base + nj * 8 + (lane & 3) * 2;
            float b0 = bias[col], b1 = bias[col + 1];
            float v00 = acc[ti][nj][0] + b0, v01 = acc[ti][nj][1] + b1;
            float v10 = acc[ti][nj][2] + b0, v11 = acc[ti][nj][3] + b1;
            if (EPI == 1) {
                v00 = gelu_tanh(v00); v01 = gelu_tanh(v01);
                v10 = gelu_tanh(v10); v11 = gelu_tanh(v11);
            }
            size_t o0 = (size_t)r0 * N + col;
            size_t o1 = (size_t)(r0 + 8) * N + col;
            if (EPI == 2) {
                v00 += Res[o0]; v01 += Res[o0 + 1];
                v10 += Res[o1]; v11 += Res[o1 + 1];
            }
            if (STOREF) {
                float2 f0; f0.x = v00; f0.y = v01;
                float2 f1; f1.x = v10; f1.y = v11;
                *(float2*)(C + o0) = f0;
                *(float2*)(C + o1) = f1;
            }
            if (STOREH) {
                *(uint32_t*)(Ch + o0) = packh(v00, v01);
                *(uint32_t*)(Ch + o1) = packh(v10, v11);
            }
        }
    }
}

// ---------------- Flash attention, fp16 tensor cores ----------------
// Br=128 (8 warps), Bc=64. qkv fp16 [row][3C].
#define FAP 72
#define FA_Q_ELEMS (128 * FAP)
#define FA_KV_ELEMS (64 * FAP)
#define FA2_SMEM ((FA_Q_ELEMS + 4 * FA_KV_ELEMS) * 2)

__global__ __launch_bounds__(256, 2) void flash_attn_tc(
    const __half* __restrict__ qkv, __half* __restrict__ outp)
{
    extern __shared__ __half sb[];
    __half* sQ = sb;                       // [128][72]
    __half* sKV = sQ + FA_Q_ELEMS;         // [2][K,V][64][72]

    const int tid = threadIdx.x, lane = tid & 31, w = tid >> 5;
    const int b = blockIdx.z, h = blockIdx.y, qtb = blockIdx.x;
    const int q0 = qtb * 128;
    const size_t rs = 3 * CDIM;
    const __half* base = qkv + (size_t)b * TSEQ * rs + h * HD;

#pragma unroll
    for (int i = 0; i < 4; i++) {
        int id = tid + i * 256;
        int r = id >> 3, c8 = id & 7;
        cp16(smem_u32(sQ + r * FAP + c8 * 8), base + (size_t)(q0 + r) * rs + c8 * 8);
    }

    auto loadKV = [&](int kt, int buf) {
        const int k0 = kt * 64;
        __half* d = sKV + buf * 2 * FA_KV_ELEMS;
        const __half* srcs[2] = { base + CDIM, base + 2 * CDIM };
#pragma unroll
        for (int a = 0; a < 2; a++) {
#pragma unroll
            for (int i = 0; i < 2; i++) {
                int id = tid + i * 256;
                int r = id >> 3, c8 = id & 7;
                cp16(smem_u32(d + a * FA_KV_ELEMS + r * FAP + c8 * 8),
                     srcs[a] + (size_t)(k0 + r) * rs + c8 * 8);
            }
        }
    };

    loadKV(0, 0);
    cp_commit();

    float o[8][4];
#pragma unroll
    for (int nt = 0; nt < 8; nt++)
#pragma unroll
        for (int e = 0; e < 4; e++) o[nt][e] = 0.0f;
    float m[2] = {-1e30f, -1e30f}, l[2] = {0.0f, 0.0f};
    uint32_t qf[4][4];

    const int ktmax = 2 * qtb + 1;
    const int rmin = q0 + w * 16;
    const int rmax = rmin + 15;

    for (int kt = 0; kt <= ktmax; kt++) {
        const int buf = kt & 1;
        if (kt < ktmax) {
            loadKV(kt + 1, buf ^ 1);
            cp_commit();
            cp_wait<1>();
        } else {
            cp_wait<0>();
        }
        __syncthreads();

        if (kt == 0) {
#pragma unroll
            for (int ks = 0; ks < 4; ks++) {
                uint32_t off = (uint32_t)((w * 16 + (lane & 15)) * FAP
                                          + ks * 16 + (lane >> 4) * 8) * 2;
                ldsm_x4(qf[ks], smem_u32(sQ) + off);
            }
        }

        const int k0 = kt * 64;
        if (k0 <= rmax) {
            __half* Kt = sKV + buf * 2 * FA_KV_ELEMS;
            __half* Vt = Kt + FA_KV_ELEMS;

            float s[8][4];
#pragma unroll
            for (int nt = 0; nt < 8; nt++)
#pragma unroll
                for (int e = 0; e < 4; e++) s[nt][e] = 0.0f;

            // S = Q K^T
#pragma unroll
            for (int ks = 0; ks < 4; ks++) {
                uint32_t kb[8][2];
#pragma unroll
                for (int p = 0; p < 4; p++) {
                    uint32_t roff = (uint32_t)((p * 16 + ((lane >> 4) << 3) + (lane & 7)) * FAP
                                               + ks * 16 + (((lane >> 3) & 1) << 3)) * 2;
                    uint32_t r4[4];
                    ldsm_x4(r4, smem_u32(Kt) + roff);
                    kb[2 * p][0] = r4[0]; kb[2 * p][1] = r4[1];
                    kb[2 * p + 1][0] = r4[2]; kb[2 * p + 1][1] = r4[3];
                }
#pragma unroll
                for (int t = 0; t < 8; t++) mma16816(s[t], qf[ks], kb[t]);
            }

            const float SC = 0.18033688011112042f;  // 0.125 * log2(e)
#pragma unroll
            for (int nt = 0; nt < 8; nt++)
#pragma unroll
                for (int e = 0; e < 4; e++) s[nt][e] *= SC;

            if (k0 + 63 > rmin) {
#pragma unroll
                for (int nt = 0; nt < 8; nt++)
#pragma unroll
                    for (int e = 0; e < 4; e++) {
                        int col = k0 + nt * 8 + 2 * (lane & 3) + (e & 1);
                        int rr = rmin + (lane >> 2) + (e >> 1) * 8;
                        if (col > rr) s[nt][e] = -1e30f;
                    }
            }

#pragma unroll
            for (int half = 0; half < 2; half++) {
                float tm = -1e30f;
#pragma unroll
                for (int nt = 0; nt < 8; nt++)
                    tm = fmaxf(tm, fmaxf(s[nt][2 * half], s[nt][2 * half + 1]));
                tm = fmaxf(tm, __shfl_xor_sync(0xffffffffu, tm, 1));
                tm = fmaxf(tm, __shfl_xor_sync(0xffffffffu, tm, 2));
                float mn = fmaxf(m[half], tm);
                float alpha = fast_ex2(m[half] - mn);
                m[half] = mn;
                float ps = 0.0f;
#pragma unroll
                for (int nt = 0; nt < 8; nt++) {
                    s[nt][2 * half]     = fast_ex2(s[nt][2 * half] - mn);
                    s[nt][2 * half + 1] = fast_ex2(s[nt][2 * half + 1] - mn);
                    ps += s[nt][2 * half] + s[nt][2 * half + 1];
                }
                l[half] = l[half] * alpha + ps;
#pragma unroll
                for (int nt = 0; nt < 8; nt++) {
                    o[nt][2 * half]     *= alpha;
                    o[nt][2 * half + 1] *= alpha;
                }
            }

            // O += P V
#pragma unroll
            for (int ks = 0; ks < 4; ks++) {
                uint32_t pa[4];
                pa[0] = packh(s[2 * ks][0],     s[2 * ks][1]);
                pa[1] = packh(s[2 * ks][2],     s[2 * ks][3]);
                pa[2] = packh(s[2 * ks + 1][0], s[2 * ks + 1][1]);
                pa[3] = packh(s[2 * ks + 1][2], s[2 * ks + 1][3]);
                uint32_t vb[8][2];
#pragma unroll
                for (int p = 0; p < 4; p++) {
                    uint32_t roff = (uint32_t)((ks * 16 + (lane & 15)) * FAP
                                               + p * 16 + (lane >> 4) * 8) * 2;
                    uint32_t r4[4];
                    ldsm_x4t(r4, smem_u32(Vt) + roff);
                    vb[2 * p][0] = r4[0]; vb[2 * p][1] = r4[1];
                    vb[2 * p + 1][0] = r4[2]; vb[2 * p + 1][1] = r4[3];
                }
#pragma unroll
                for (int t = 0; t < 8; t++) mma16816(o[t], pa, vb[t]);
            }
        }
        __syncthreads();
    }

    float linv[2];
#pragma unroll
    for (int half = 0; half < 2; half++) {
        float lv = l[half];
        lv += __shfl_xor_sync(0xffffffffu, lv, 1);
        lv += __shfl_xor_sync(0xffffffffu, lv, 2);
        linv[half] = 1.0f / lv;
    }
#pragma unroll
    for (int nt = 0; nt < 8; nt++) {
#pragma unroll
        for (int half = 0; half < 2; half++) {
            int rowg = q0 + w * 16 + (lane >> 2) + half * 8;
            int colg = h * HD + nt * 8 + 2 * (lane & 3);
            float f0 = o[nt][2 * half]     * linv[half];
            float f1 = o[nt][2 * half + 1] * linv[half];
            size_t off = (size_t)(b * TSEQ + rowg) * CDIM + colg;
            *(uint32_t*)(outp + off) = packh(f0, f1);
        }
    }
}

// ---------------- launch ----------------
extern "C" void kernel_launch(void* const* d_in, const int* in_sizes, int n_in,
                              void* d_out, int out_size)
{
    const float* x       = (const float*)d_in[0];
    const float* ln1_w   = (const float*)d_in[1];
    const float* ln1_b   = (const float*)d_in[2];
    const float* attn_w  = (const float*)d_in[3];
    const float* attn_b  = (const float*)d_in[4];
    const float* proj_w  = (const float*)d_in[5];
    const float* proj_b  = (const float*)d_in[6];
    const float* ln2_w   = (const float*)d_in[7];
    const float* ln2_b   = (const float*)d_in[8];
    const float* fc_w    = (const float*)d_in[9];
    const float* fc_b    = (const float*)d_in[10];
    const float* mproj_w = (const float*)d_in[11];
    const float* mproj_b = (const float*)d_in[12];
    float* out = (float*)d_out;

    __half *ln, *qkv, *att, *fc, *wv;
    float *x1;
    cudaGetSymbolAddress((void**)&ln,  g_ln);
    cudaGetSymbolAddress((void**)&qkv, g_qkv);
    cudaGetSymbolAddress((void**)&att, g_att);
    cudaGetSymbolAddress((void**)&x1,  g_x1);
    cudaGetSymbolAddress((void**)&fc,  g_fc);
    cudaGetSymbolAddress((void**)&wv,  g_w);

    __half *wqkv = wv;
    __half *wproj = wv + W_QKV_N;
    __half *wfc = wproj + W_PROJ_N;
    __half *wmp = wfc + W_FC_N;

    cudaFuncSetAttribute(flash_attn_tc,
                         cudaFuncAttributeMaxDynamicSharedMemorySize, FA2_SMEM);
    cudaFuncSetAttribute((const void*)hgemm<0, false, true>,
                         cudaFuncAttributeMaxDynamicSharedMemorySize, GEMM_SMEM_BYTES);
    cudaFuncSetAttribute((const void*)hgemm<2, true, false>,
                         cudaFuncAttributeMaxDynamicSharedMemorySize, GEMM_SMEM_BYTES);
    cudaFuncSetAttribute((const void*)hgemm<1, false, true>,
                         cudaFuncAttributeMaxDynamicSharedMemorySize, GEMM_SMEM_BYTES);

    // 0) convert all weights to fp16 (single launch)
    cvt_all_kernel<<<(N4_TOTAL + 255) / 256, 256>>>(
        (const float4*)attn_w, (const float4*)proj_w,
        (const float4*)fc_w, (const float4*)mproj_w, (uint32_t*)wv);

    // 1) ln1 -> fp16
    ln_kernel<<<MROWS, 256>>>(x, ln1_w, ln1_b, ln);
    // 2) qkv = ln1 @ W_attn + b   [8192, 2304] -> fp16
    hgemm<0, false, true><<<dim3(2304 / 128, MROWS / 128), 256, GEMM_SMEM_BYTES>>>(
        MROWS, 2304, CDIM, ln, wqkv, attn_b, nullptr, nullptr, qkv);
    // 3) attention -> fp16
    flash_attn_tc<<<dim3(TSEQ / 128, NHEAD, NBATCH), 256, FA2_SMEM>>>(qkv, att);
    // 4) x1 = x + att @ W_proj + b   (fp32)
    hgemm<2, true, false><<<dim3(CDIM / 128, MROWS / 128), 256, GEMM_SMEM_BYTES>>>(
        MROWS, CDIM, CDIM, att, wproj, proj_b, x, x1, nullptr);
    // 5) ln2 -> fp16
    ln_kernel<<<MROWS, 256>>>(x1, ln2_w, ln2_b, ln);
    // 6) fc = gelu(ln2 @ W_fc + b)   [8192, 3072] -> fp16
    hgemm<1, false, true><<<dim3(3072 / 128, MROWS / 128), 256, GEMM_SMEM_BYTES>>>(
        MROWS, 3072, CDIM, ln, wfc, fc_b, nullptr, nullptr, fc);
    // 7) out = x1 + fc @ W_mproj + b   (fp32)
    hgemm<2, true, false><<<dim3(CDIM / 128, MROWS / 128), 256, GEMM_SMEM_BYTES>>>(
        MROWS, CDIM, 4 * CDIM, fc, wmp, mproj_b, x1, out, nullptr);
}

// round 10
// speedup vs baseline: 2.7970x; 1.0066x over previous
#include <cuda_runtime.h>
#include <cuda_fp16.h>
#include <math.h>
#include <stdint.h>

#define MROWS 8192           // B*T = 4*2048
#define CDIM  768
#define TSEQ  2048
#define NBATCH 4
#define NHEAD 12
#define HD    64

// ---------------- scratch (no allocations allowed) ----------------
__device__ __half g_ln [(size_t)MROWS * CDIM];
__device__ __half g_qkv[(size_t)MROWS * 3 * CDIM];
__device__ __half g_att[(size_t)MROWS * CDIM];
__device__ float  g_x1 [(size_t)MROWS * CDIM];
__device__ __half g_fc [(size_t)MROWS * 4 * CDIM];

#define W_QKV_N (768*2304)
#define W_PROJ_N (768*768)
#define W_FC_N (768*3072)
#define W_MP_N (3072*768)
__device__ __half g_w[W_QKV_N + W_PROJ_N + W_FC_N + W_MP_N];

// ---------------- helpers ----------------
__device__ __forceinline__ float warp_sum(float v) {
#pragma unroll
    for (int m = 16; m; m >>= 1) v += __shfl_xor_sync(0xffffffffu, v, m);
    return v;
}

__device__ __forceinline__ float fast_ex2(float x) {
    float y;
    asm("ex2.approx.ftz.f32 %0, %1;" : "=f"(y) : "f"(x));
    return y;
}
__device__ __forceinline__ float fast_rcp(float x) {
    float y;
    asm("rcp.approx.ftz.f32 %0, %1;" : "=f"(y) : "f"(x));
    return y;
}

__device__ __forceinline__ float gelu_tanh(float x) {
    // tanh(u) = 1 - 2/(exp2(2u*log2e)+1)
    const float c = 0.7978845608028654f;  // sqrt(2/pi)
    float u = c * (x + 0.044715f * x * x * x);
    float t = fast_ex2(2.885390081777927f * u);   // exp(2u)
    float th = 1.0f - 2.0f * fast_rcp(t + 1.0f);
    return 0.5f * x * (1.0f + th);
}

__device__ __forceinline__ uint32_t smem_u32(const void* p) {
    return (uint32_t)__cvta_generic_to_shared(p);
}

__device__ __forceinline__ void cp16(uint32_t dst, const void* src) {
    asm volatile("cp.async.cg.shared.global [%0], [%1], 16;\n" :: "r"(dst), "l"(src));
}
__device__ __forceinline__ void cp_commit() { asm volatile("cp.async.commit_group;\n"); }
template<int N> __device__ __forceinline__ void cp_wait() {
    asm volatile("cp.async.wait_group %0;\n" :: "n"(N));
}

__device__ __forceinline__ void ldsm_x4(uint32_t (&r)[4], uint32_t addr) {
    asm volatile("ldmatrix.sync.aligned.m8n8.x4.shared.b16 {%0,%1,%2,%3}, [%4];"
        : "=r"(r[0]), "=r"(r[1]), "=r"(r[2]), "=r"(r[3]) : "r"(addr));
}
__device__ __forceinline__ void ldsm_x4t(uint32_t (&r)[4], uint32_t addr) {
    asm volatile("ldmatrix.sync.aligned.m8n8.x4.trans.shared.b16 {%0,%1,%2,%3}, [%4];"
        : "=r"(r[0]), "=r"(r[1]), "=r"(r[2]), "=r"(r[3]) : "r"(addr));
}
__device__ __forceinline__ void mma16816(float (&d)[4], const uint32_t (&a)[4],
                                         const uint32_t (&b)[2]) {
    asm volatile(
        "mma.sync.aligned.m16n8k16.row.col.f32.f16.f16.f32 "
        "{%0,%1,%2,%3},{%4,%5,%6,%7},{%8,%9},{%0,%1,%2,%3};"
        : "+f"(d[0]), "+f"(d[1]), "+f"(d[2]), "+f"(d[3])
        : "r"(a[0]), "r"(a[1]), "r"(a[2]), "r"(a[3]), "r"(b[0]), "r"(b[1]));
}

__device__ __forceinline__ uint32_t packh(float a, float b) {
    __half2 h = __floats2half2_rn(a, b);
    return *(uint32_t*)&h;
}

// ---------------- fused weight convert f32 -> fp16 (one launch) ------
#define N4_QKV (W_QKV_N / 4)
#define N4_PROJ (W_PROJ_N / 4)
#define N4_FC (W_FC_N / 4)
#define N4_MP (W_MP_N / 4)
#define N4_TOTAL (N4_QKV + N4_PROJ + N4_FC + N4_MP)

__global__ __launch_bounds__(256) void cvt_all_kernel(
    const float4* __restrict__ w0, const float4* __restrict__ w1,
    const float4* __restrict__ w2, const float4* __restrict__ w3,
    uint32_t* __restrict__ h)
{
    int i = blockIdx.x * 256 + threadIdx.x;
    if (i >= N4_TOTAL) return;
    const float4* src;
    int j = i;
    if (j < N4_QKV) { src = w0; }
    else if ((j -= N4_QKV) < N4_PROJ) { src = w1; }
    else if ((j -= N4_PROJ) < N4_FC) { src = w2; }
    else { j -= N4_FC; src = w3; }
    float4 v = src[j];
    h[2 * i]     = packh(v.x, v.y);
    h[2 * i + 1] = packh(v.z, v.w);
}

// ---------------- LayerNorm (row = 768, ddof=1) -> fp16 --------
__global__ __launch_bounds__(256) void ln_kernel(
    const float* __restrict__ x, const float* __restrict__ w,
    const float* __restrict__ b, __half* __restrict__ y)
{
    const int row = blockIdx.x;
    const float* xr = x + (size_t)row * CDIM;
    const int t = threadIdx.x;

    float v0 = xr[t], v1 = xr[t + 256], v2 = xr[t + 512];
    float s  = v0 + v1 + v2;
    float s2 = v0 * v0 + v1 * v1 + v2 * v2;

    __shared__ float sh[2][8];
    s = warp_sum(s); s2 = warp_sum(s2);
    int wid = t >> 5, lane = t & 31;
    if (lane == 0) { sh[0][wid] = s; sh[1][wid] = s2; }
    __syncthreads();
    if (wid == 0) {
        float a = (lane < 8) ? sh[0][lane] : 0.0f;
        float c = (lane < 8) ? sh[1][lane] : 0.0f;
        a = warp_sum(a); c = warp_sum(c);
        if (lane == 0) { sh[0][0] = a; sh[1][0] = c; }
    }
    __syncthreads();
    s = sh[0][0]; s2 = sh[1][0];

    float mean = s * (1.0f / (float)CDIM);
    float var  = (s2 - (float)CDIM * mean * mean) * (1.0f / (float)(CDIM - 1));
    float rstd = rsqrtf(var + 1e-5f);

    size_t base = (size_t)row * CDIM;
#pragma unroll
    for (int j = 0; j < 3; j++) {
        int c = t + j * 256;
        float v = (j == 0 ? v0 : (j == 1 ? v1 : v2));
        y[base + c] = __float2half_rn((v - mean) * rstd * w[c] + b[c]);
    }
}

// ---------------- fp16 tensor-core GEMM, 128x128x32 ----------------
#define GEMM_SMEM_ELEMS ((2*128*40) + (2*32*136))
#define GEMM_SMEM_BYTES (GEMM_SMEM_ELEMS * 2)

template<int EPI, bool STOREF, bool STOREH>
__global__ __launch_bounds__(256, 2) void hgemm(
    int M, int N, int K,
    const __half* __restrict__ A, const __half* __restrict__ B,
    const float* __restrict__ bias, const float* __restrict__ Res,
    float* __restrict__ C, __half* __restrict__ Ch)
{
    extern __shared__ __half sm[];
    __half* sA = sm;                    // [2][128][40]
    __half* sB = sA + 2 * 128 * 40;     // [2][32][136]
    const uint32_t uA = smem_u32(sA), uB = smem_u32(sB);

    const int tid  = threadIdx.x;
    const int warp = tid >> 5, lane = tid & 31;
    const int wr = warp >> 1, wc = warp & 1;
    const int bm = blockIdx.y * 128, bn = blockIdx.x * 128;

    float acc[2][8][4];
#pragma unroll
    for (int i = 0; i < 2; i++)
#pragma unroll
        for (int j = 0; j < 8; j++)
#pragma unroll
            for (int k = 0; k < 4; k++) acc[i][j][k] = 0.0f;

    auto load_tile = [&](int kt, int buf) {
#pragma unroll
        for (int i = 0; i < 2; i++) {
            int id = tid + i * 256;
            int r = id >> 2, c = id & 3;
            uint32_t off = (uint32_t)((buf * 128 + r) * 40 + c * 8) * 2;
            cp16(uA + off, A + (size_t)(bm + r) * K + kt * 32 + c * 8);
        }
#pragma unroll
        for (int i = 0; i < 2; i++) {
            int id = tid + i * 256;
            int r = id >> 4, c = id & 15;
            uint32_t off = (uint32_t)((buf * 32 + r) * 136 + c * 8) * 2;
            cp16(uB + off, B + (size_t)(kt * 32 + r) * N + bn + c * 8);
        }
    };

    const int KT = K >> 5;
    load_tile(0, 0);
    cp_commit();

    for (int kt = 0; kt < KT; ++kt) {
        const int buf = kt & 1;
        if (kt + 1 < KT) {
            load_tile(kt + 1, buf ^ 1);
            cp_commit();
            cp_wait<1>();
        } else {
            cp_wait<0>();
        }
        __syncthreads();

#pragma unroll
        for (int ks = 0; ks < 2; ++ks) {
            uint32_t a[2][4], b[8][2];
#pragma unroll
            for (int ti = 0; ti < 2; ++ti) {
                int r = wr * 32 + ti * 16 + (lane & 15);
                int col = ks * 16 + (lane >> 4) * 8;
                ldsm_x4(a[ti], uA + (uint32_t)((buf * 128 + r) * 40 + col) * 2);
            }
#pragma unroll
            for (int p = 0; p < 4; ++p) {
                int kr = ks * 16 + (lane & 15);
                int col = wc * 64 + p * 16 + (lane >> 4) * 8;
                uint32_t r4[4];
                ldsm_x4t(r4, uB + (uint32_t)((buf * 32 + kr) * 136 + col) * 2);
                b[2 * p][0] = r4[0]; b[2 * p][1] = r4[1];
                b[2 * p + 1][0] = r4[2]; b[2 * p + 1][1] = r4[3];
            }
#pragma unroll
            for (int ti = 0; ti < 2; ++ti)
#pragma unroll
                for (int nj = 0; nj < 8; ++nj)
                    mma16816(acc[ti][nj], a[ti], b[nj]);
        }
        __syncthreads();
    }

    const int row_base = bm + wr * 32;
    const int col_base = bn + wc * 64;
#pragma unroll
    for (int ti = 0; ti < 2; ++ti) {
        int r0 = row_base + ti * 16 + (lane >> 2);
#pragma unroll
        for (int nj = 0; nj < 8; ++nj) {
            int col = col_base + nj * 8 + (lane & 3) * 2;
            float b0 = bias[col], b1 = bias[col + 1];
            float v00 = acc[ti][nj][0] + b0, v01 = acc[ti][nj][1] + b1;
            float v10 = acc[ti][nj][2] + b0, v11 = acc[ti][nj][3] + b1;
            if (EPI == 1) {
                v00 = gelu_tanh(v00); v01 = gelu_tanh(v01);
                v10 = gelu_tanh(v10); v11 = gelu_tanh(v11);
            }
            size_t o0 = (size_t)r0 * N + col;
            size_t o1 = (size_t)(r0 + 8) * N + col;
            if (EPI == 2) {
                v00 += Res[o0]; v01 += Res[o0 + 1];
                v10 += Res[o1]; v11 += Res[o1 + 1];
            }
            if (STOREF) {
                float2 f0; f0.x = v00; f0.y = v01;
                float2 f1; f1.x = v10; f1.y = v11;
                *(float2*)(C + o0) = f0;
                *(float2*)(C + o1) = f1;
            }
            if (STOREH) {
                *(uint32_t*)(Ch + o0) = packh(v00, v01);
                *(uint32_t*)(Ch + o1) = packh(v10, v11);
            }
        }
    }
}

// ---------------- Flash attention, fp16 tensor cores ----------------
// Br=128 (8 warps), Bc=64. 4-stage KV ring, 1 barrier per 2 tiles.
#define FAP 72
#define FA_Q_ELEMS (128 * FAP)
#define FA_KV_ELEMS (64 * FAP)
#define FA2_SMEM ((FA_Q_ELEMS + 8 * FA_KV_ELEMS) * 2)   // Q + 4 stages x (K,V)

__global__ __launch_bounds__(256, 2) void flash_attn_tc(
    const __half* __restrict__ qkv, __half* __restrict__ outp)
{
    extern __shared__ __half sb[];
    __half* sQ = sb;                       // [128][72]
    __half* sKV = sQ + FA_Q_ELEMS;         // [4][K,V][64][72]

    const int tid = threadIdx.x, lane = tid & 31, w = tid >> 5;
    const int b = blockIdx.z, h = blockIdx.y;
    const int qtb = (gridDim.x - 1) - blockIdx.x;   // heavy tiles first
    const int q0 = qtb * 128;
    const size_t rs = 3 * CDIM;
    const __half* base = qkv + (size_t)b * TSEQ * rs + h * HD;

    auto loadKV = [&](int kt) {
        const int k0 = kt * 64;
        __half* d = sKV + (kt & 3) * 2 * FA_KV_ELEMS;
        const __half* srcs[2] = { base + CDIM, base + 2 * CDIM };
#pragma unroll
        for (int a = 0; a < 2; a++) {
#pragma unroll
            for (int i = 0; i < 2; i++) {
                int id = tid + i * 256;
                int r = id >> 3, c8 = id & 7;
                cp16(smem_u32(d + a * FA_KV_ELEMS + r * FAP + c8 * 8),
                     srcs[a] + (size_t)(k0 + r) * rs + c8 * 8);
            }
        }
    };

    // prologue: Q + first pair of KV tiles, one group
#pragma unroll
    for (int i = 0; i < 4; i++) {
        int id = tid + i * 256;
        int r = id >> 3, c8 = id & 7;
        cp16(smem_u32(sQ + r * FAP + c8 * 8), base + (size_t)(q0 + r) * rs + c8 * 8);
    }
    loadKV(0);
    loadKV(1);
    cp_commit();

    float o[8][4];
#pragma unroll
    for (int nt = 0; nt < 8; nt++)
#pragma unroll
        for (int e = 0; e < 4; e++) o[nt][e] = 0.0f;
    float m[2] = {-1e30f, -1e30f}, l[2] = {0.0f, 0.0f};
    uint32_t qf[4][4];

    const int NT = 2 * qtb + 2;          // always even
    const int rmin = q0 + w * 16;
    const int rmax = rmin + 15;

    for (int kt0 = 0; kt0 < NT; kt0 += 2) {
        cp_wait<0>();
        __syncthreads();
        if (kt0 + 2 < NT) {
            loadKV(kt0 + 2);
            loadKV(kt0 + 3);
            cp_commit();
        }
        if (kt0 == 0) {
#pragma unroll
            for (int ks = 0; ks < 4; ks++) {
                uint32_t off = (uint32_t)((w * 16 + (lane & 15)) * FAP
                                          + ks * 16 + (lane >> 4) * 8) * 2;
                ldsm_x4(qf[ks], smem_u32(sQ) + off);
            }
        }

#pragma unroll
        for (int sub = 0; sub < 2; sub++) {
            const int kt = kt0 + sub;
            const int k0 = kt * 64;
            if (k0 > rmax) continue;
            __half* Kt = sKV + (kt & 3) * 2 * FA_KV_ELEMS;
            __half* Vt = Kt + FA_KV_ELEMS;

            float s[8][4];
#pragma unroll
            for (int nt = 0; nt < 8; nt++)
#pragma unroll
                for (int e = 0; e < 4; e++) s[nt][e] = 0.0f;

            // S = Q K^T
#pragma unroll
            for (int ks = 0; ks < 4; ks++) {
                uint32_t kb[8][2];
#pragma unroll
                for (int p = 0; p < 4; p++) {
                    uint32_t roff = (uint32_t)((p * 16 + ((lane >> 4) << 3) + (lane & 7)) * FAP
                                               + ks * 16 + (((lane >> 3) & 1) << 3)) * 2;
                    uint32_t r4[4];
                    ldsm_x4(r4, smem_u32(Kt) + roff);
                    kb[2 * p][0] = r4[0]; kb[2 * p][1] = r4[1];
                    kb[2 * p + 1][0] = r4[2]; kb[2 * p + 1][1] = r4[3];
                }
#pragma unroll
                for (int t = 0; t < 8; t++) mma16816(s[t], qf[ks], kb[t]);
            }

            const float SC = 0.18033688011112042f;  // 0.125 * log2(e)
#pragma unroll
            for (int nt = 0; nt < 8; nt++)
#pragma unroll
                for (int e = 0; e < 4; e++) s[nt][e] *= SC;

            if (k0 + 63 > rmin) {
#pragma unroll
                for (int nt = 0; nt < 8; nt++)
#pragma unroll
                    for (int e = 0; e < 4; e++) {
                        int col = k0 + nt * 8 + 2 * (lane & 3) + (e & 1);
                        int rr = rmin + (lane >> 2) + (e >> 1) * 8;
                        if (col > rr) s[nt][e] = -1e30f;
                    }
            }

#pragma unroll
            for (int half = 0; half < 2; half++) {
                float tm = -1e30f;
#pragma unroll
                for (int nt = 0; nt < 8; nt++)
                    tm = fmaxf(tm, fmaxf(s[nt][2 * half], s[nt][2 * half + 1]));
                tm = fmaxf(tm, __shfl_xor_sync(0xffffffffu, tm, 1));
                tm = fmaxf(tm, __shfl_xor_sync(0xffffffffu, tm, 2));
                float mn = fmaxf(m[half], tm);
                float alpha = fast_ex2(m[half] - mn);
                m[half] = mn;
                float ps = 0.0f;
#pragma unroll
                for (int nt = 0; nt < 8; nt++) {
                    s[nt][2 * half]     = fast_ex2(s[nt][2 * half] - mn);
                    s[nt][2 * half + 1] = fast_ex2(s[nt][2 * half + 1] - mn);
                    ps += s[nt][2 * half] + s[nt][2 * half + 1];
                }
                l[half] = l[half] * alpha + ps;
#pragma unroll
                for (int nt = 0; nt < 8; nt++) {
                    o[nt][2 * half]     *= alpha;
                    o[nt][2 * half + 1] *= alpha;
                }
            }

            // O += P V
#pragma unroll
            for (int ks = 0; ks < 4; ks++) {
                uint32_t pa[4];
                pa[0] = packh(s[2 * ks][0],     s[2 * ks][1]);
                pa[1] = packh(s[2 * ks][2],     s[2 * ks][3]);
                pa[2] = packh(s[2 * ks + 1][0], s[2 * ks + 1][1]);
                pa[3] = packh(s[2 * ks + 1][2], s[2 * ks + 1][3]);
                uint32_t vb[8][2];
#pragma unroll
                for (int p = 0; p < 4; p++) {
                    uint32_t roff = (uint32_t)((ks * 16 + (lane & 15)) * FAP
                                               + p * 16 + (lane >> 4) * 8) * 2;
                    uint32_t r4[4];
                    ldsm_x4t(r4, smem_u32(Vt) + roff);
                    vb[2 * p][0] = r4[0]; vb[2 * p][1] = r4[1];
                    vb[2 * p + 1][0] = r4[2]; vb[2 * p + 1][1] = r4[3];
                }
#pragma unroll
                for (int t = 0; t < 8; t++) mma16816(o[t], pa, vb[t]);
            }
        }
    }

    float linv[2];
#pragma unroll
    for (int half = 0; half < 2; half++) {
        float lv = l[half];
        lv += __shfl_xor_sync(0xffffffffu, lv, 1);
        lv += __shfl_xor_sync(0xffffffffu, lv, 2);
        linv[half] = 1.0f / lv;
    }
#pragma unroll
    for (int nt = 0; nt < 8; nt++) {
#pragma unroll
        for (int half = 0; half < 2; half++) {
            int rowg = q0 + w * 16 + (lane >> 2) + half * 8;
            int colg = h * HD + nt * 8 + 2 * (lane & 3);
            float f0 = o[nt][2 * half]     * linv[half];
            float f1 = o[nt][2 * half + 1] * linv[half];
            size_t off = (size_t)(b * TSEQ + rowg) * CDIM + colg;
            *(uint32_t*)(outp + off) = packh(f0, f1);
        }
    }
}

// ---------------- launch ----------------
extern "C" void kernel_launch(void* const* d_in, const int* in_sizes, int n_in,
                              void* d_out, int out_size)
{
    const float* x       = (const float*)d_in[0];
    const float* ln1_w   = (const float*)d_in[1];
    const float* ln1_b   = (const float*)d_in[2];
    const float* attn_w  = (const float*)d_in[3];
    const float* attn_b  = (const float*)d_in[4];
    const float* proj_w  = (const float*)d_in[5];
    const float* proj_b  = (const float*)d_in[6];
    const float* ln2_w   = (const float*)d_in[7];
    const float* ln2_b   = (const float*)d_in[8];
    const float* fc_w    = (const float*)d_in[9];
    const float* fc_b    = (const float*)d_in[10];
    const float* mproj_w = (const float*)d_in[11];
    const float* mproj_b = (const float*)d_in[12];
    float* out = (float*)d_out;

    __half *ln, *qkv, *att, *fc, *wv;
    float *x1;
    cudaGetSymbolAddress((void**)&ln,  g_ln);
    cudaGetSymbolAddress((void**)&qkv, g_qkv);
    cudaGetSymbolAddress((void**)&att, g_att);
    cudaGetSymbolAddress((void**)&x1,  g_x1);
    cudaGetSymbolAddress((void**)&fc,  g_fc);
    cudaGetSymbolAddress((void**)&wv,  g_w);

    __half *wqkv = wv;
    __half *wproj = wv + W_QKV_N;
    __half *wfc = wproj + W_PROJ_N;
    __half *wmp = wfc + W_FC_N;

    cudaFuncSetAttribute(flash_attn_tc,
                         cudaFuncAttributeMaxDynamicSharedMemorySize, FA2_SMEM);
    cudaFuncSetAttribute((const void*)hgemm<0, false, true>,
                         cudaFuncAttributeMaxDynamicSharedMemorySize, GEMM_SMEM_BYTES);
    cudaFuncSetAttribute((const void*)hgemm<2, true, false>,
                         cudaFuncAttributeMaxDynamicSharedMemorySize, GEMM_SMEM_BYTES);
    cudaFuncSetAttribute((const void*)hgemm<1, false, true>,
                         cudaFuncAttributeMaxDynamicSharedMemorySize, GEMM_SMEM_BYTES);

    // 0) convert all weights to fp16 (single launch)
    cvt_all_kernel<<<(N4_TOTAL + 255) / 256, 256>>>(
        (const float4*)attn_w, (const float4*)proj_w,
        (const float4*)fc_w, (const float4*)mproj_w, (uint32_t*)wv);

    // 1) ln1 -> fp16
    ln_kernel<<<MROWS, 256>>>(x, ln1_w, ln1_b, ln);
    // 2) qkv = ln1 @ W_attn + b   [8192, 2304] -> fp16
    hgemm<0, false, true><<<dim3(2304 / 128, MROWS / 128), 256, GEMM_SMEM_BYTES>>>(
        MROWS, 2304, CDIM, ln, wqkv, attn_b, nullptr, nullptr, qkv);
    // 3) attention -> fp16
    flash_attn_tc<<<dim3(TSEQ / 128, NHEAD, NBATCH), 256, FA2_SMEM>>>(qkv, att);
    // 4) x1 = x + att @ W_proj + b   (fp32)
    hgemm<2, true, false><<<dim3(CDIM / 128, MROWS / 128), 256, GEMM_SMEM_BYTES>>>(
        MROWS, CDIM, CDIM, att, wproj, proj_b, x, x1, nullptr);
    // 5) ln2 -> fp16
    ln_kernel<<<MROWS, 256>>>(x1, ln2_w, ln2_b, ln);
    // 6) fc = gelu(ln2 @ W_fc + b)   [8192, 3072] -> fp16
    hgemm<1, false, true><<<dim3(3072 / 128, MROWS / 128), 256, GEMM_SMEM_BYTES>>>(
        MROWS, 3072, CDIM, ln, wfc, fc_b, nullptr, nullptr, fc);
    // 7) out = x1 + fc @ W_mproj + b   (fp32)
    hgemm<2, true, false><<<dim3(CDIM / 128, MROWS / 128), 256, GEMM_SMEM_BYTES>>>(
        MROWS, CDIM, 4 * CDIM, fc, wmp, mproj_b, x1, out, nullptr);
}